// round 1
// baseline (speedup 1.0000x reference)
#include <cuda_runtime.h>
#include <math_constants.h>

#define N_TOT 8192
#define D_DIM 128

// scratch (allocation-free rule: device globals)
__device__ float g_th[N_TOT * D_DIM];   // theta_mat [8192][128] (== flat [B,Cb,H,W])
__device__ float g_ph[N_TOT * D_DIM];   // phi flat; viewed as [128][8192]
__device__ float g_gm[N_TOT * D_DIM];   // g_mat [8192][128]
__device__ float g_o [N_TOT * D_DIM];   // attn output [8192][128] (== flat [B,Cb,H,W])

// ---------------------------------------------------------------------------
// Projections: out[b,m,hw] = sum_c W[m,c] * x[b,c,hw] + bias[m]
// grid (16, 2, 24): x = hw tile (64), y = m tile (64), z = b*3 + proj
// ---------------------------------------------------------------------------
__global__ void proj_kernel(const float* __restrict__ x,
                            const float* __restrict__ tw, const float* __restrict__ tb,
                            const float* __restrict__ pw, const float* __restrict__ pb,
                            const float* __restrict__ gw, const float* __restrict__ gb)
{
    const int n0 = blockIdx.x * 64;
    const int m0 = blockIdx.y * 64;
    const int z  = blockIdx.z;
    const int b = z / 3, proj = z % 3;

    const float* W; const float* bias; float* out;
    if (proj == 0)      { W = tw; bias = tb; out = g_th; }
    else if (proj == 1) { W = pw; bias = pb; out = g_ph; }
    else                { W = gw; bias = gb; out = g_gm; }
    out += b * (128 * 1024);
    const float* xb = x + b * (256 * 1024);

    __shared__ float Ws[16][68];
    __shared__ float Xs[16][68];

    const int tid = threadIdx.x;
    const int tx = tid & 15, ty = tid >> 4;

    float acc[4][4] = {};
    for (int k0 = 0; k0 < 256; k0 += 16) {
        for (int idx = tid; idx < 1024; idx += 256) {
            int k = idx >> 6, m = idx & 63;
            Ws[k][m] = W[(m0 + m) * 256 + k0 + k];
        }
        for (int idx = tid; idx < 1024; idx += 256) {
            int k = idx >> 6, n = idx & 63;
            Xs[k][n] = xb[(k0 + k) * 1024 + n0 + n];
        }
        __syncthreads();
        #pragma unroll
        for (int k = 0; k < 16; ++k) {
            float4 a  = *(const float4*)&Ws[k][ty * 4];
            float4 bq = *(const float4*)&Xs[k][tx * 4];
            float av[4] = {a.x, a.y, a.z, a.w};
            float bv[4] = {bq.x, bq.y, bq.z, bq.w};
            #pragma unroll
            for (int i = 0; i < 4; ++i)
                #pragma unroll
                for (int j = 0; j < 4; ++j)
                    acc[i][j] += av[i] * bv[j];
        }
        __syncthreads();
    }
    #pragma unroll
    for (int i = 0; i < 4; ++i) {
        int m = m0 + ty * 4 + i;
        float bv = bias[m];
        #pragma unroll
        for (int j = 0; j < 4; ++j)
            out[m * 1024 + n0 + tx * 4 + j] = acc[i][j] + bv;
    }
}

// ---------------------------------------------------------------------------
// Flash attention over the reshaped matrices:
//   S[n,m] = sum_k g_th[n*128+k] * g_ph[k*8192+m]
//   P = softmax_row(S);  g_o[n,:] = P @ g_mat   (g_mat[m,k] = g_gm[m*128+k])
// One CTA per 64-row Q block; loop over 128 K/G tiles of 64 columns.
// ---------------------------------------------------------------------------
#define QS_STRIDE 68
#define KS_STRIDE 68
#define PS_STRIDE 68
#define GS_STRIDE 132
#define ATTN_SMEM ((128*QS_STRIDE + 128*KS_STRIDE + 64*PS_STRIDE + 64*GS_STRIDE) * 4)

__global__ void attn_kernel()
{
    extern __shared__ float smem[];
    float* Qs = smem;                       // [128][QS_STRIDE]  Qs[k][r]
    float* Ks = Qs + 128 * QS_STRIDE;       // [128][KS_STRIDE]  Ks[k][j]
    float* Ps = Ks + 128 * KS_STRIDE;       // [64][PS_STRIDE]
    float* Gs = Ps + 64  * PS_STRIDE;       // [64][GS_STRIDE]   Gs[n][d]

    const int tid = threadIdx.x;
    const int tx = tid & 15, ty = tid >> 4;
    const int row0 = blockIdx.x * 64;

    // load Q transposed (once)
    for (int idx = tid; idx < 64 * 128; idx += 256) {
        int r = idx >> 7, k = idx & 127;
        Qs[k * QS_STRIDE + r] = g_th[(row0 + r) * 128 + k];
    }

    float m[4], l[4], o[4][8];
    #pragma unroll
    for (int i = 0; i < 4; ++i) {
        m[i] = -CUDART_INF_F; l[i] = 0.f;
        #pragma unroll
        for (int j = 0; j < 8; ++j) o[i][j] = 0.f;
    }
    __syncthreads();

    for (int c0 = 0; c0 < N_TOT; c0 += 64) {
        // load K tile: Ks[k][j] = phi_mat[k][c0+j]
        for (int idx = tid; idx < 128 * 64; idx += 256) {
            int k = idx >> 6, j = idx & 63;
            Ks[k * KS_STRIDE + j] = g_ph[k * N_TOT + c0 + j];
        }
        // load G tile: Gs[n][d] = g_mat[c0+n][d]
        for (int idx = tid; idx < 64 * 128; idx += 256) {
            int n = idx >> 7, d = idx & 127;
            Gs[n * GS_STRIDE + d] = g_gm[(c0 + n) * 128 + d];
        }
        __syncthreads();

        // S tile: 4x4 per thread
        float s[4][4] = {};
        #pragma unroll 8
        for (int k = 0; k < 128; ++k) {
            float4 q  = *(const float4*)&Qs[k * QS_STRIDE + ty * 4];
            float4 kk = *(const float4*)&Ks[k * KS_STRIDE + tx * 4];
            float qa[4] = {q.x, q.y, q.z, q.w};
            float ka[4] = {kk.x, kk.y, kk.z, kk.w};
            #pragma unroll
            for (int i = 0; i < 4; ++i)
                #pragma unroll
                for (int j = 0; j < 4; ++j)
                    s[i][j] += qa[i] * ka[j];
        }

        // online softmax; row group = 16 consecutive lanes (same ty, half-warp)
        #pragma unroll
        for (int i = 0; i < 4; ++i) {
            float mt = fmaxf(fmaxf(s[i][0], s[i][1]), fmaxf(s[i][2], s[i][3]));
            #pragma unroll
            for (int off = 8; off; off >>= 1)
                mt = fmaxf(mt, __shfl_xor_sync(0xffffffffu, mt, off));
            float mn = fmaxf(m[i], mt);
            float corr = exp2f((m[i] - mn) * 1.44269504f);
            float rs = 0.f;
            #pragma unroll
            for (int j = 0; j < 4; ++j) {
                float p = exp2f((s[i][j] - mn) * 1.44269504f);
                s[i][j] = p; rs += p;
            }
            #pragma unroll
            for (int off = 8; off; off >>= 1)
                rs += __shfl_xor_sync(0xffffffffu, rs, off);
            l[i] = l[i] * corr + rs;
            m[i] = mn;
            #pragma unroll
            for (int j = 0; j < 8; ++j) o[i][j] *= corr;
            *(float4*)&Ps[(ty * 4 + i) * PS_STRIDE + tx * 4] =
                make_float4(s[i][0], s[i][1], s[i][2], s[i][3]);
        }
        __syncthreads();

        // PV: o[i][j] += sum_n P[r][n] * Gs[n][tx*8+j]
        #pragma unroll 4
        for (int n4 = 0; n4 < 16; ++n4) {
            float4 pr[4];
            #pragma unroll
            for (int i = 0; i < 4; ++i)
                pr[i] = *(const float4*)&Ps[(ty * 4 + i) * PS_STRIDE + n4 * 4];
            #pragma unroll
            for (int u = 0; u < 4; ++u) {
                int n = n4 * 4 + u;
                float4 ga = *(const float4*)&Gs[n * GS_STRIDE + tx * 8];
                float4 gb = *(const float4*)&Gs[n * GS_STRIDE + tx * 8 + 4];
                float gv[8] = {ga.x, ga.y, ga.z, ga.w, gb.x, gb.y, gb.z, gb.w};
                #pragma unroll
                for (int i = 0; i < 4; ++i) {
                    float p = (u == 0) ? pr[i].x : (u == 1) ? pr[i].y
                            : (u == 2) ? pr[i].z : pr[i].w;
                    #pragma unroll
                    for (int j = 0; j < 8; ++j) o[i][j] += p * gv[j];
                }
            }
        }
        __syncthreads();
    }

    // epilogue: normalize and write
    #pragma unroll
    for (int i = 0; i < 4; ++i) {
        float inv = 1.f / l[i];
        int row = row0 + ty * 4 + i;
        float4 v0 = make_float4(o[i][0]*inv, o[i][1]*inv, o[i][2]*inv, o[i][3]*inv);
        float4 v1 = make_float4(o[i][4]*inv, o[i][5]*inv, o[i][6]*inv, o[i][7]*inv);
        *(float4*)&g_o[row * 128 + tx * 8]     = v0;
        *(float4*)&g_o[row * 128 + tx * 8 + 4] = v1;
    }
}

// ---------------------------------------------------------------------------
// Output projection + residual:
//   y[b,m,hw] = sum_k W_w[m,k] * O[b,k,hw] + W_b[m] + x[b,m,hw]
// grid (16, 4, 8): x = hw tile, y = m tile (M=256), z = b
// ---------------------------------------------------------------------------
__global__ void outproj_kernel(const float* __restrict__ x,
                               const float* __restrict__ Ww, const float* __restrict__ Wb,
                               float* __restrict__ y)
{
    const int n0 = blockIdx.x * 64;
    const int m0 = blockIdx.y * 64;
    const int b  = blockIdx.z;
    const float* Ob = g_o + b * (128 * 1024);
    const float* xb = x + b * (256 * 1024);
    float* yb = y + b * (256 * 1024);

    __shared__ float Ws[16][68];
    __shared__ float Bs[16][68];
    const int tid = threadIdx.x;
    const int tx = tid & 15, ty = tid >> 4;

    float acc[4][4] = {};
    for (int k0 = 0; k0 < 128; k0 += 16) {
        for (int idx = tid; idx < 1024; idx += 256) {
            int k = idx >> 6, m = idx & 63;
            Ws[k][m] = Ww[(m0 + m) * 128 + k0 + k];
        }
        for (int idx = tid; idx < 1024; idx += 256) {
            int k = idx >> 6, n = idx & 63;
            Bs[k][n] = Ob[(k0 + k) * 1024 + n0 + n];
        }
        __syncthreads();
        #pragma unroll
        for (int k = 0; k < 16; ++k) {
            float4 a  = *(const float4*)&Ws[k][ty * 4];
            float4 bq = *(const float4*)&Bs[k][tx * 4];
            float av[4] = {a.x, a.y, a.z, a.w};
            float bv[4] = {bq.x, bq.y, bq.z, bq.w};
            #pragma unroll
            for (int i = 0; i < 4; ++i)
                #pragma unroll
                for (int j = 0; j < 4; ++j)
                    acc[i][j] += av[i] * bv[j];
        }
        __syncthreads();
    }
    #pragma unroll
    for (int i = 0; i < 4; ++i) {
        int mm = m0 + ty * 4 + i;
        float bv = Wb[mm];
        #pragma unroll
        for (int j = 0; j < 4; ++j) {
            int nn = n0 + tx * 4 + j;
            yb[mm * 1024 + nn] = acc[i][j] + bv + xb[mm * 1024 + nn];
        }
    }
}

// ---------------------------------------------------------------------------
extern "C" void kernel_launch(void* const* d_in, const int* in_sizes, int n_in,
                              void* d_out, int out_size)
{
    const float* x  = (const float*)d_in[0];
    const float* tw = (const float*)d_in[1];
    const float* tb = (const float*)d_in[2];
    const float* pw = (const float*)d_in[3];
    const float* pb = (const float*)d_in[4];
    const float* gw = (const float*)d_in[5];
    const float* gb = (const float*)d_in[6];
    const float* Ww = (const float*)d_in[7];
    const float* Wb = (const float*)d_in[8];
    float* y = (float*)d_out;

    cudaFuncSetAttribute(attn_kernel,
                         cudaFuncAttributeMaxDynamicSharedMemorySize, ATTN_SMEM);

    proj_kernel<<<dim3(16, 2, 24), 256>>>(x, tw, tb, pw, pb, gw, gb);
    attn_kernel<<<dim3(128), 256, ATTN_SMEM>>>();
    outproj_kernel<<<dim3(16, 4, 8), 256>>>(x, Ww, Wb, y);
}

// round 2
// speedup vs baseline: 2.8448x; 2.8448x over previous
#include <cuda_runtime.h>

#define N_TOT 8192
#define D_DIM 128
#define L2E 1.4426950408889634f
#define NEG_INF (-1.0f/0.0f)

// scratch (allocation-free rule: device globals)
__device__ float g_th[N_TOT * D_DIM];   // theta_mat [8192][128]
__device__ float g_ph[N_TOT * D_DIM];   // phi, viewed as [128][8192]
__device__ float g_gm[N_TOT * D_DIM];   // g_mat [8192][128]
__device__ float g_o [N_TOT * D_DIM];   // attn output [8192][128]

// ---------------------------------------------------------------------------
// helpers
// ---------------------------------------------------------------------------
__device__ __forceinline__ unsigned tf32_rna(float x) {
    unsigned u;
    asm("cvt.rna.tf32.f32 %0, %1;" : "=r"(u) : "f"(x));
    return u;
}

__device__ __forceinline__ void mma_tf32(float c[4],
    unsigned a0, unsigned a1, unsigned a2, unsigned a3,
    unsigned b0, unsigned b1)
{
    asm volatile(
        "mma.sync.aligned.m16n8k8.row.col.f32.tf32.tf32.f32 "
        "{%0,%1,%2,%3}, {%4,%5,%6,%7}, {%8,%9}, {%0,%1,%2,%3};\n"
        : "+f"(c[0]), "+f"(c[1]), "+f"(c[2]), "+f"(c[3])
        : "r"(a0), "r"(a1), "r"(a2), "r"(a3), "r"(b0), "r"(b1));
}

// ---------------------------------------------------------------------------
// Projections: out[b,m,hw] = sum_c W[m,c]*x[b,c,hw] + bias[m]
// ---------------------------------------------------------------------------
__global__ void proj_kernel(const float* __restrict__ x,
                            const float* __restrict__ tw, const float* __restrict__ tb,
                            const float* __restrict__ pw, const float* __restrict__ pb,
                            const float* __restrict__ gw, const float* __restrict__ gb)
{
    const int n0 = blockIdx.x * 64;
    const int m0 = blockIdx.y * 64;
    const int z  = blockIdx.z;
    const int b = z / 3, proj = z % 3;

    const float* W; const float* bias; float* out;
    if (proj == 0)      { W = tw; bias = tb; out = g_th; }
    else if (proj == 1) { W = pw; bias = pb; out = g_ph; }
    else                { W = gw; bias = gb; out = g_gm; }
    out += b * (128 * 1024);
    const float* xb = x + b * (256 * 1024);

    __shared__ float Ws[16][68];
    __shared__ float Xs[16][68];

    const int tid = threadIdx.x;
    const int tx = tid & 15, ty = tid >> 4;

    float acc[4][4] = {};
    for (int k0 = 0; k0 < 256; k0 += 16) {
        for (int idx = tid; idx < 1024; idx += 256) {
            int k = idx >> 6, m = idx & 63;
            Ws[k][m] = W[(m0 + m) * 256 + k0 + k];
        }
        for (int idx = tid; idx < 1024; idx += 256) {
            int k = idx >> 6, n = idx & 63;
            Xs[k][n] = xb[(k0 + k) * 1024 + n0 + n];
        }
        __syncthreads();
        #pragma unroll
        for (int k = 0; k < 16; ++k) {
            float4 a  = *(const float4*)&Ws[k][ty * 4];
            float4 bq = *(const float4*)&Xs[k][tx * 4];
            float av[4] = {a.x, a.y, a.z, a.w};
            float bv[4] = {bq.x, bq.y, bq.z, bq.w};
            #pragma unroll
            for (int i = 0; i < 4; ++i)
                #pragma unroll
                for (int j = 0; j < 4; ++j)
                    acc[i][j] += av[i] * bv[j];
        }
        __syncthreads();
    }
    #pragma unroll
    for (int i = 0; i < 4; ++i) {
        int m = m0 + ty * 4 + i;
        float bv = bias[m];
        #pragma unroll
        for (int j = 0; j < 4; ++j)
            out[m * 1024 + n0 + tx * 4 + j] = acc[i][j] + bv;
    }
}

// ---------------------------------------------------------------------------
// Flash attention with tf32 mma.sync.
//   S = theta @ phi  (2xTF32: A split hi/lo), P = softmax, O = P @ G (1xTF32)
// 128 CTAs x 256 thr. Per CTA: 64 Q rows, stream KV in tiles of 128.
// Warps: 4 rows x 2 cols. Each warp: S[16][64]; O partial [16][128] over its
// 64-wide KV slice; partials summed in epilogue.
// ---------------------------------------------------------------------------
#define QS_ST 132
#define KS_ST 136
#define GS_ST 136
#define PS_ST 132
#define ATTN_SMEM ((64*QS_ST + 128*KS_ST + 128*GS_ST + 64*PS_ST + 256) * 4)

__global__ void __launch_bounds__(256, 1) attn_mma_kernel()
{
    extern __shared__ float smf[];
    float* Qs = smf;                       // [64][132]
    float* Ks = Qs + 64 * QS_ST;           // [128][136]  Ks[k_d][n_kv]
    float* Gs = Ks + 128 * KS_ST;          // [128][136]  Gs[kv][d]
    float* Ps = Gs + 128 * GS_ST;          // [64][132]
    float* red_max = Ps + 64 * PS_ST;      // [2][64]
    float* red_sum = red_max + 128;        // [2][64]

    const int tid  = threadIdx.x;
    const int lane = tid & 31, warp = tid >> 5;
    const int wr = warp >> 1, wc = warp & 1;
    const int grp = lane >> 2, qid = lane & 3;
    const int r_lo = wr * 16 + grp, r_hi = r_lo + 8;
    const int cw0 = wc * 64;
    const int row0 = blockIdx.x * 64;

    // load Q block once
    for (int idx = tid; idx < 64 * 32; idx += 256) {
        int r = idx >> 5, k4 = (idx & 31) << 2;
        *(float4*)&Qs[r * QS_ST + k4] = *(const float4*)&g_th[(row0 + r) * 128 + k4];
    }

    float m0 = NEG_INF, m1 = NEG_INF, l0 = 0.f, l1 = 0.f;
    float o[16][4];
    #pragma unroll
    for (int t = 0; t < 16; ++t) { o[t][0]=0.f; o[t][1]=0.f; o[t][2]=0.f; o[t][3]=0.f; }

    for (int c0 = 0; c0 < N_TOT; c0 += 128) {
        // tile loads (128 KV cols): Ks[k][n], Gs[kv][d]
        for (int idx = tid; idx < 128 * 32; idx += 256) {
            int k = idx >> 5, n4 = (idx & 31) << 2;
            *(float4*)&Ks[k * KS_ST + n4] = *(const float4*)&g_ph[k * N_TOT + c0 + n4];
        }
        for (int idx = tid; idx < 128 * 32; idx += 256) {
            int kv = idx >> 5, d4 = (idx & 31) << 2;
            *(float4*)&Gs[kv * GS_ST + d4] = *(const float4*)&g_gm[(c0 + kv) * 128 + d4];
        }
        __syncthreads();

        // ---- S = Q @ K (2xTF32 split on A) ----
        float s[8][4];
        #pragma unroll
        for (int t = 0; t < 8; ++t) { s[t][0]=0.f; s[t][1]=0.f; s[t][2]=0.f; s[t][3]=0.f; }

        #pragma unroll
        for (int ks = 0; ks < 16; ++ks) {
            const int k = ks * 8;
            float af0 = Qs[r_lo * QS_ST + k + qid];
            float af1 = Qs[r_hi * QS_ST + k + qid];
            float af2 = Qs[r_lo * QS_ST + k + qid + 4];
            float af3 = Qs[r_hi * QS_ST + k + qid + 4];
            unsigned ah0 = tf32_rna(af0), ah1 = tf32_rna(af1);
            unsigned ah2 = tf32_rna(af2), ah3 = tf32_rna(af3);
            unsigned al0 = tf32_rna(af0 - __uint_as_float(ah0));
            unsigned al1 = tf32_rna(af1 - __uint_as_float(ah1));
            unsigned al2 = tf32_rna(af2 - __uint_as_float(ah2));
            unsigned al3 = tf32_rna(af3 - __uint_as_float(ah3));
            #pragma unroll
            for (int t = 0; t < 8; ++t) {
                const float* kp = &Ks[(k + qid) * KS_ST + cw0 + t * 8 + grp];
                unsigned b0 = tf32_rna(kp[0]);
                unsigned b1 = tf32_rna(kp[4 * KS_ST]);
                mma_tf32(s[t], ah0, ah1, ah2, ah3, b0, b1);
                mma_tf32(s[t], al0, al1, al2, al3, b0, b1);
            }
        }

        // ---- online softmax ----
        float mx0 = NEG_INF, mx1 = NEG_INF;
        #pragma unroll
        for (int t = 0; t < 8; ++t) {
            mx0 = fmaxf(mx0, fmaxf(s[t][0], s[t][1]));
            mx1 = fmaxf(mx1, fmaxf(s[t][2], s[t][3]));
        }
        mx0 = fmaxf(mx0, __shfl_xor_sync(0xffffffffu, mx0, 1));
        mx0 = fmaxf(mx0, __shfl_xor_sync(0xffffffffu, mx0, 2));
        mx1 = fmaxf(mx1, __shfl_xor_sync(0xffffffffu, mx1, 1));
        mx1 = fmaxf(mx1, __shfl_xor_sync(0xffffffffu, mx1, 2));
        if (qid == 0) {
            red_max[wc * 64 + r_lo] = mx0;
            red_max[wc * 64 + r_hi] = mx1;
        }
        __syncthreads();
        float mn0 = fmaxf(m0, fmaxf(red_max[r_lo], red_max[64 + r_lo]));
        float mn1 = fmaxf(m1, fmaxf(red_max[r_hi], red_max[64 + r_hi]));
        float corr0 = exp2f((m0 - mn0) * L2E);
        float corr1 = exp2f((m1 - mn1) * L2E);
        m0 = mn0; m1 = mn1;

        float sum0 = 0.f, sum1 = 0.f;
        #pragma unroll
        for (int t = 0; t < 8; ++t) {
            float p00 = __uint_as_float(tf32_rna(exp2f((s[t][0] - mn0) * L2E)));
            float p01 = __uint_as_float(tf32_rna(exp2f((s[t][1] - mn0) * L2E)));
            float p10 = __uint_as_float(tf32_rna(exp2f((s[t][2] - mn1) * L2E)));
            float p11 = __uint_as_float(tf32_rna(exp2f((s[t][3] - mn1) * L2E)));
            sum0 += p00 + p01;
            sum1 += p10 + p11;
            int col = cw0 + t * 8 + 2 * qid;
            *(float2*)&Ps[r_lo * PS_ST + col] = make_float2(p00, p01);
            *(float2*)&Ps[r_hi * PS_ST + col] = make_float2(p10, p11);
        }
        sum0 += __shfl_xor_sync(0xffffffffu, sum0, 1);
        sum0 += __shfl_xor_sync(0xffffffffu, sum0, 2);
        sum1 += __shfl_xor_sync(0xffffffffu, sum1, 1);
        sum1 += __shfl_xor_sync(0xffffffffu, sum1, 2);
        if (qid == 0) {
            red_sum[wc * 64 + r_lo] = sum0;
            red_sum[wc * 64 + r_hi] = sum1;
        }
        __syncthreads();
        l0 = l0 * corr0 + red_sum[r_lo] + red_sum[64 + r_lo];
        l1 = l1 * corr1 + red_sum[r_hi] + red_sum[64 + r_hi];
        #pragma unroll
        for (int t = 0; t < 16; ++t) {
            o[t][0] *= corr0; o[t][1] *= corr0;
            o[t][2] *= corr1; o[t][3] *= corr1;
        }

        // ---- O += P @ G (1xTF32) over this warp-col's 64 KV slice ----
        #pragma unroll
        for (int ks = 0; ks < 8; ++ks) {
            const int kv = cw0 + ks * 8;
            unsigned a0 = __float_as_uint(Ps[r_lo * PS_ST + kv + qid]);
            unsigned a1 = __float_as_uint(Ps[r_hi * PS_ST + kv + qid]);
            unsigned a2 = __float_as_uint(Ps[r_lo * PS_ST + kv + qid + 4]);
            unsigned a3 = __float_as_uint(Ps[r_hi * PS_ST + kv + qid + 4]);
            #pragma unroll
            for (int t = 0; t < 16; ++t) {
                const float* gp = &Gs[(kv + qid) * GS_ST + t * 8 + grp];
                unsigned b0 = tf32_rna(gp[0]);
                unsigned b1 = tf32_rna(gp[4 * GS_ST]);
                mma_tf32(o[t], a0, a1, a2, a3, b0, b1);
            }
        }
        __syncthreads();
    }

    // ---- epilogue: sum warp-col partials, normalize, store ----
    if (wc == 1) {
        #pragma unroll
        for (int t = 0; t < 16; ++t) {
            int col = t * 8 + 2 * qid;
            *(float2*)&Ps[r_lo * PS_ST + col] = make_float2(o[t][0], o[t][1]);
            *(float2*)&Ps[r_hi * PS_ST + col] = make_float2(o[t][2], o[t][3]);
        }
    }
    __syncthreads();
    if (wc == 0) {
        float inv0 = 1.f / l0, inv1 = 1.f / l1;
        #pragma unroll
        for (int t = 0; t < 16; ++t) {
            int col = t * 8 + 2 * qid;
            float2 q0 = *(float2*)&Ps[r_lo * PS_ST + col];
            float2 q1 = *(float2*)&Ps[r_hi * PS_ST + col];
            *(float2*)&g_o[(row0 + r_lo) * 128 + col] =
                make_float2((o[t][0] + q0.x) * inv0, (o[t][1] + q0.y) * inv0);
            *(float2*)&g_o[(row0 + r_hi) * 128 + col] =
                make_float2((o[t][2] + q1.x) * inv1, (o[t][3] + q1.y) * inv1);
        }
    }
}

// ---------------------------------------------------------------------------
// Output projection + residual
// ---------------------------------------------------------------------------
__global__ void outproj_kernel(const float* __restrict__ x,
                               const float* __restrict__ Ww, const float* __restrict__ Wb,
                               float* __restrict__ y)
{
    const int n0 = blockIdx.x * 64;
    const int m0 = blockIdx.y * 64;
    const int b  = blockIdx.z;
    const float* Ob = g_o + b * (128 * 1024);
    const float* xb = x + b * (256 * 1024);
    float* yb = y + b * (256 * 1024);

    __shared__ float Ws[16][68];
    __shared__ float Bs[16][68];
    const int tid = threadIdx.x;
    const int tx = tid & 15, ty = tid >> 4;

    float acc[4][4] = {};
    for (int k0 = 0; k0 < 128; k0 += 16) {
        for (int idx = tid; idx < 1024; idx += 256) {
            int k = idx >> 6, m = idx & 63;
            Ws[k][m] = Ww[(m0 + m) * 128 + k0 + k];
        }
        for (int idx = tid; idx < 1024; idx += 256) {
            int k = idx >> 6, n = idx & 63;
            Bs[k][n] = Ob[(k0 + k) * 1024 + n0 + n];
        }
        __syncthreads();
        #pragma unroll
        for (int k = 0; k < 16; ++k) {
            float4 a  = *(const float4*)&Ws[k][ty * 4];
            float4 bq = *(const float4*)&Bs[k][tx * 4];
            float av[4] = {a.x, a.y, a.z, a.w};
            float bv[4] = {bq.x, bq.y, bq.z, bq.w};
            #pragma unroll
            for (int i = 0; i < 4; ++i)
                #pragma unroll
                for (int j = 0; j < 4; ++j)
                    acc[i][j] += av[i] * bv[j];
        }
        __syncthreads();
    }
    #pragma unroll
    for (int i = 0; i < 4; ++i) {
        int mm = m0 + ty * 4 + i;
        float bv = Wb[mm];
        #pragma unroll
        for (int j = 0; j < 4; ++j) {
            int nn = n0 + tx * 4 + j;
            yb[mm * 1024 + nn] = acc[i][j] + bv + xb[mm * 1024 + nn];
        }
    }
}

// ---------------------------------------------------------------------------
extern "C" void kernel_launch(void* const* d_in, const int* in_sizes, int n_in,
                              void* d_out, int out_size)
{
    const float* x  = (const float*)d_in[0];
    const float* tw = (const float*)d_in[1];
    const float* tb = (const float*)d_in[2];
    const float* pw = (const float*)d_in[3];
    const float* pb = (const float*)d_in[4];
    const float* gw = (const float*)d_in[5];
    const float* gb = (const float*)d_in[6];
    const float* Ww = (const float*)d_in[7];
    const float* Wb = (const float*)d_in[8];
    float* y = (float*)d_out;

    cudaFuncSetAttribute(attn_mma_kernel,
                         cudaFuncAttributeMaxDynamicSharedMemorySize, ATTN_SMEM);

    proj_kernel<<<dim3(16, 2, 24), 256>>>(x, tw, tb, pw, pb, gw, gb);
    attn_mma_kernel<<<dim3(128), 256, ATTN_SMEM>>>();
    outproj_kernel<<<dim3(16, 4, 8), 256>>>(x, Ww, Wb, y);
}

// round 3
// speedup vs baseline: 4.5903x; 1.6136x over previous
#include <cuda_runtime.h>

#define N_TOT 8192
#define D_DIM 128
#define L2E 1.4426950408889634f
#define NEG_INF (-1.0f/0.0f)

// scratch (allocation-free rule: device globals)
__device__ float g_th[N_TOT * D_DIM];   // theta, flat [B,Cb,HW] == [8192][128]
__device__ float g_ph[N_TOT * D_DIM];   // phi,   flat; viewed as [128][8192]
__device__ float g_gm[N_TOT * D_DIM];   // g,     flat == [8192][128]
__device__ float g_o [N_TOT * D_DIM];   // attn out, flat [B,Cb,HW]

// ---------------------------------------------------------------------------
// helpers
// ---------------------------------------------------------------------------
__device__ __forceinline__ unsigned tf32_rna(float x) {
    unsigned u;
    asm("cvt.rna.tf32.f32 %0, %1;" : "=r"(u) : "f"(x));
    return u;
}

__device__ __forceinline__ void mma_tf32(float c[4],
    unsigned a0, unsigned a1, unsigned a2, unsigned a3,
    unsigned b0, unsigned b1)
{
    asm volatile(
        "mma.sync.aligned.m16n8k8.row.col.f32.tf32.tf32.f32 "
        "{%0,%1,%2,%3}, {%4,%5,%6,%7}, {%8,%9}, {%0,%1,%2,%3};\n"
        : "+f"(c[0]), "+f"(c[1]), "+f"(c[2]), "+f"(c[3])
        : "r"(a0), "r"(a1), "r"(a2), "r"(a3), "r"(b0), "r"(b1));
}

__device__ __forceinline__ void cp16(unsigned smem_addr, const void* gptr) {
    asm volatile("cp.async.cg.shared.global [%0], [%1], 16;\n"
                 :: "r"(smem_addr), "l"(gptr));
}
#define CP_COMMIT() asm volatile("cp.async.commit_group;\n" ::: "memory")
#define CP_WAIT(n)  asm volatile("cp.async.wait_group %0;\n" :: "n"(n) : "memory")

// ---------------------------------------------------------------------------
// Fused projections (theta/phi/g), tf32 MMA 2x-split.
// grid (16 n-tiles of 64, 3 projs, 8 batches), 128 threads (4 warps 2m x 2n).
// out[b,m,hw] = sum_c W[m,c]*x[b,c,hw] + bias[m]
// ---------------------------------------------------------------------------
__global__ void __launch_bounds__(128) proj_mma_kernel(
    const float* __restrict__ x,
    const float* __restrict__ tw, const float* __restrict__ tb,
    const float* __restrict__ pw, const float* __restrict__ pb,
    const float* __restrict__ gw, const float* __restrict__ gb)
{
    __shared__ float Wt[128 * 36];   // A tile [m=128][k=32], stride 36 (A-pattern)
    __shared__ float Xt[32 * 72];    // B tile [k=32][n=64],  stride 72 (B-pattern)

    const int n0 = blockIdx.x * 64;
    const int proj = blockIdx.y;
    const int b = blockIdx.z;

    const float* W; const float* bias; float* out;
    if (proj == 0)      { W = tw; bias = tb; out = g_th; }
    else if (proj == 1) { W = pw; bias = pb; out = g_ph; }
    else                { W = gw; bias = gb; out = g_gm; }
    out += b * 131072;
    const float* xb = x + b * 262144;

    const int tid = threadIdx.x, lane = tid & 31, warp = tid >> 5;
    const int grp = lane >> 2, qid = lane & 3;
    const int m0w = (warp >> 1) * 64, n0w = (warp & 1) * 32;

    float acc[16][4];
    #pragma unroll
    for (int i = 0; i < 16; ++i) { acc[i][0]=0.f; acc[i][1]=0.f; acc[i][2]=0.f; acc[i][3]=0.f; }

    for (int k0 = 0; k0 < 256; k0 += 32) {
        #pragma unroll
        for (int idx = tid; idx < 128 * 8; idx += 128) {
            int m = idx >> 3, k4 = (idx & 7) << 2;
            *(float4*)&Wt[m * 36 + k4] = *(const float4*)&W[m * 256 + k0 + k4];
        }
        #pragma unroll
        for (int idx = tid; idx < 32 * 16; idx += 128) {
            int k = idx >> 4, n4 = (idx & 15) << 2;
            *(float4*)&Xt[k * 72 + n4] = *(const float4*)&xb[(k0 + k) * 1024 + n0 + n4];
        }
        __syncthreads();
        #pragma unroll
        for (int ks = 0; ks < 4; ++ks) {
            const int k = ks * 8;
            unsigned ah[4][4], al[4][4];
            #pragma unroll
            for (int mi = 0; mi < 4; ++mi) {
                int r = m0w + mi * 16 + grp;
                float f0 = Wt[r * 36 + k + qid];
                float f1 = Wt[(r + 8) * 36 + k + qid];
                float f2 = Wt[r * 36 + k + qid + 4];
                float f3 = Wt[(r + 8) * 36 + k + qid + 4];
                ah[mi][0] = tf32_rna(f0); al[mi][0] = tf32_rna(f0 - __uint_as_float(ah[mi][0]));
                ah[mi][1] = tf32_rna(f1); al[mi][1] = tf32_rna(f1 - __uint_as_float(ah[mi][1]));
                ah[mi][2] = tf32_rna(f2); al[mi][2] = tf32_rna(f2 - __uint_as_float(ah[mi][2]));
                ah[mi][3] = tf32_rna(f3); al[mi][3] = tf32_rna(f3 - __uint_as_float(ah[mi][3]));
            }
            #pragma unroll
            for (int ni = 0; ni < 4; ++ni) {
                int c = n0w + ni * 8 + grp;
                unsigned b0 = tf32_rna(Xt[(k + qid) * 72 + c]);
                unsigned b1 = tf32_rna(Xt[(k + qid + 4) * 72 + c]);
                #pragma unroll
                for (int mi = 0; mi < 4; ++mi) {
                    mma_tf32(acc[mi*4+ni], ah[mi][0], ah[mi][1], ah[mi][2], ah[mi][3], b0, b1);
                    mma_tf32(acc[mi*4+ni], al[mi][0], al[mi][1], al[mi][2], al[mi][3], b0, b1);
                }
            }
        }
        __syncthreads();
    }
    #pragma unroll
    for (int mi = 0; mi < 4; ++mi) {
        int m = m0w + mi * 16 + grp;
        float bv0 = bias[m], bv1 = bias[m + 8];
        #pragma unroll
        for (int ni = 0; ni < 4; ++ni) {
            int n = n0 + n0w + ni * 8 + 2 * qid;
            float* a = acc[mi*4+ni];
            *(float2*)&out[m * 1024 + n]       = make_float2(a[0] + bv0, a[1] + bv0);
            *(float2*)&out[(m + 8) * 1024 + n] = make_float2(a[2] + bv1, a[3] + bv1);
        }
    }
}

// ---------------------------------------------------------------------------
// Flash attention, tf32 mma.sync, cp.async-pipelined tile loads,
// per-warp-column softmax state (merged in epilogue).
// 128 CTAs x 256 thr; 64 Q rows/CTA; KV tiles of 128.
// ---------------------------------------------------------------------------
#define QS_ST 132
#define KS_ST 136
#define GS_ST 136
#define PS_ST 132
#define ATTN_SMEM ((64*QS_ST + 128*KS_ST + 128*GS_ST + 64*PS_ST + 128) * 4)

__global__ void __launch_bounds__(256, 1) attn_mma_kernel()
{
    extern __shared__ float smf[];
    float* Qs = smf;                       // [64][132]  Qs[r][k]
    float* Ks = Qs + 64 * QS_ST;           // [128][136] Ks[k_d][n_kv]
    float* Gs = Ks + 128 * KS_ST;          // [128][136] Gs[kv][d]
    float* Ps = Gs + 128 * GS_ST;          // [64][132]
    float* red_m = Ps + 64 * PS_ST;        // [64]
    float* red_l = red_m + 64;             // [64]

    const int tid  = threadIdx.x;
    const int lane = tid & 31, warp = tid >> 5;
    const int wr = warp >> 1, wc = warp & 1;
    const int grp = lane >> 2, qid = lane & 3;
    const int r_lo = wr * 16 + grp, r_hi = r_lo + 8;
    const int cw0 = wc * 64;
    const int row0 = blockIdx.x * 64;

    const unsigned ks_u = (unsigned)__cvta_generic_to_shared(Ks);
    const unsigned gs_u = (unsigned)__cvta_generic_to_shared(Gs);

    // prologue: start K(0), G(0) streams
    #pragma unroll
    for (int idx = tid; idx < 128 * 32; idx += 256) {
        int k = idx >> 5, n4 = (idx & 31) << 2;
        cp16(ks_u + (k * KS_ST + n4) * 4, &g_ph[k * N_TOT + n4]);
    }
    CP_COMMIT();
    #pragma unroll
    for (int idx = tid; idx < 128 * 32; idx += 256) {
        int kv = idx >> 5, d4 = (idx & 31) << 2;
        cp16(gs_u + (kv * GS_ST + d4) * 4, &g_gm[kv * 128 + d4]);
    }
    CP_COMMIT();

    // Q block (once)
    #pragma unroll
    for (int idx = tid; idx < 64 * 32; idx += 256) {
        int r = idx >> 5, k4 = (idx & 31) << 2;
        *(float4*)&Qs[r * QS_ST + k4] = *(const float4*)&g_th[(row0 + r) * 128 + k4];
    }

    float m0 = NEG_INF, m1 = NEG_INF, l0 = 0.f, l1 = 0.f;
    float o[16][4];
    #pragma unroll
    for (int t = 0; t < 16; ++t) { o[t][0]=0.f; o[t][1]=0.f; o[t][2]=0.f; o[t][3]=0.f; }

    for (int it = 0; it < 64; ++it) {
        const int c0 = it * 128;
        CP_WAIT(1);             // K(it) ready (G(it) may still stream)
        __syncthreads();

        // ---- S = Q @ K (2xTF32 split on A) ----
        float s[8][4];
        #pragma unroll
        for (int t = 0; t < 8; ++t) { s[t][0]=0.f; s[t][1]=0.f; s[t][2]=0.f; s[t][3]=0.f; }

        #pragma unroll
        for (int ksi = 0; ksi < 16; ++ksi) {
            const int k = ksi * 8;
            float af0 = Qs[r_lo * QS_ST + k + qid];
            float af1 = Qs[r_hi * QS_ST + k + qid];
            float af2 = Qs[r_lo * QS_ST + k + qid + 4];
            float af3 = Qs[r_hi * QS_ST + k + qid + 4];
            unsigned ah0 = tf32_rna(af0), ah1 = tf32_rna(af1);
            unsigned ah2 = tf32_rna(af2), ah3 = tf32_rna(af3);
            unsigned al0 = tf32_rna(af0 - __uint_as_float(ah0));
            unsigned al1 = tf32_rna(af1 - __uint_as_float(ah1));
            unsigned al2 = tf32_rna(af2 - __uint_as_float(ah2));
            unsigned al3 = tf32_rna(af3 - __uint_as_float(ah3));
            #pragma unroll
            for (int t = 0; t < 8; ++t) {
                const float* kp = &Ks[(k + qid) * KS_ST + cw0 + t * 8 + grp];
                unsigned b0 = tf32_rna(kp[0]);
                unsigned b1 = tf32_rna(kp[4 * KS_ST]);
                mma_tf32(s[t], ah0, ah1, ah2, ah3, b0, b1);
                mma_tf32(s[t], al0, al1, al2, al3, b0, b1);
            }
        }
        __syncthreads();        // everyone done reading Ks

        if (it < 63) {          // stream K(it+1) during softmax + PV
            #pragma unroll
            for (int idx = tid; idx < 128 * 32; idx += 256) {
                int k = idx >> 5, n4 = (idx & 31) << 2;
                cp16(ks_u + (k * KS_ST + n4) * 4, &g_ph[k * N_TOT + c0 + 128 + n4]);
            }
            CP_COMMIT();
        }

        // ---- online softmax (per warp-column state) ----
        float mx0 = NEG_INF, mx1 = NEG_INF;
        #pragma unroll
        for (int t = 0; t < 8; ++t) {
            mx0 = fmaxf(mx0, fmaxf(s[t][0], s[t][1]));
            mx1 = fmaxf(mx1, fmaxf(s[t][2], s[t][3]));
        }
        mx0 = fmaxf(mx0, __shfl_xor_sync(0xffffffffu, mx0, 1));
        mx0 = fmaxf(mx0, __shfl_xor_sync(0xffffffffu, mx0, 2));
        mx1 = fmaxf(mx1, __shfl_xor_sync(0xffffffffu, mx1, 1));
        mx1 = fmaxf(mx1, __shfl_xor_sync(0xffffffffu, mx1, 2));
        float mn0 = fmaxf(m0, mx0), mn1 = fmaxf(m1, mx1);
        float corr0 = exp2f((m0 - mn0) * L2E);
        float corr1 = exp2f((m1 - mn1) * L2E);
        m0 = mn0; m1 = mn1;

        float sum0 = 0.f, sum1 = 0.f;
        #pragma unroll
        for (int t = 0; t < 8; ++t) {
            float p00 = __uint_as_float(tf32_rna(exp2f((s[t][0] - mn0) * L2E)));
            float p01 = __uint_as_float(tf32_rna(exp2f((s[t][1] - mn0) * L2E)));
            float p10 = __uint_as_float(tf32_rna(exp2f((s[t][2] - mn1) * L2E)));
            float p11 = __uint_as_float(tf32_rna(exp2f((s[t][3] - mn1) * L2E)));
            sum0 += p00 + p01;
            sum1 += p10 + p11;
            int col = cw0 + t * 8 + 2 * qid;
            *(float2*)&Ps[r_lo * PS_ST + col] = make_float2(p00, p01);
            *(float2*)&Ps[r_hi * PS_ST + col] = make_float2(p10, p11);
        }
        sum0 += __shfl_xor_sync(0xffffffffu, sum0, 1);
        sum0 += __shfl_xor_sync(0xffffffffu, sum0, 2);
        sum1 += __shfl_xor_sync(0xffffffffu, sum1, 1);
        sum1 += __shfl_xor_sync(0xffffffffu, sum1, 2);
        l0 = l0 * corr0 + sum0;
        l1 = l1 * corr1 + sum1;
        #pragma unroll
        for (int t = 0; t < 16; ++t) {
            o[t][0] *= corr0; o[t][1] *= corr0;
            o[t][2] *= corr1; o[t][3] *= corr1;
        }

        if (it < 63) CP_WAIT(1); else CP_WAIT(0);   // G(it) ready
        __syncthreads();                            // G done + P visible

        // ---- O += P @ G (1xTF32), this warp-col's 64 KV rows ----
        #pragma unroll
        for (int ksi = 0; ksi < 8; ++ksi) {
            const int kv = cw0 + ksi * 8;
            unsigned a0 = __float_as_uint(Ps[r_lo * PS_ST + kv + qid]);
            unsigned a1 = __float_as_uint(Ps[r_hi * PS_ST + kv + qid]);
            unsigned a2 = __float_as_uint(Ps[r_lo * PS_ST + kv + qid + 4]);
            unsigned a3 = __float_as_uint(Ps[r_hi * PS_ST + kv + qid + 4]);
            #pragma unroll
            for (int t = 0; t < 16; ++t) {
                const float* gp = &Gs[(kv + qid) * GS_ST + t * 8 + grp];
                unsigned b0 = tf32_rna(gp[0]);
                unsigned b1 = tf32_rna(gp[4 * GS_ST]);
                mma_tf32(o[t], a0, a1, a2, a3, b0, b1);
            }
        }
        __syncthreads();        // Gs + Ps reads done

        if (it < 63) {          // stream G(it+1) during next S
            #pragma unroll
            for (int idx = tid; idx < 128 * 32; idx += 256) {
                int kv = idx >> 5, d4 = (idx & 31) << 2;
                cp16(gs_u + (kv * GS_ST + d4) * 4, &g_gm[(c0 + 128 + kv) * 128 + d4]);
            }
            CP_COMMIT();
        }
    }

    // ---- epilogue: merge the two warp-column partials ----
    if (wc == 1) {
        if (qid == 0) {
            red_m[r_lo] = m0; red_l[r_lo] = l0;
            red_m[r_hi] = m1; red_l[r_hi] = l1;
        }
        #pragma unroll
        for (int t = 0; t < 16; ++t) {
            int col = t * 8 + 2 * qid;
            *(float2*)&Ps[r_lo * PS_ST + col] = make_float2(o[t][0], o[t][1]);
            *(float2*)&Ps[r_hi * PS_ST + col] = make_float2(o[t][2], o[t][3]);
        }
    }
    __syncthreads();
    if (wc == 0) {
        float mo0 = red_m[r_lo], lo0 = red_l[r_lo];
        float mo1 = red_m[r_hi], lo1 = red_l[r_hi];
        float mf0 = fmaxf(m0, mo0), mf1 = fmaxf(m1, mo1);
        float ca0 = exp2f((m0 - mf0) * L2E), cb0 = exp2f((mo0 - mf0) * L2E);
        float ca1 = exp2f((m1 - mf1) * L2E), cb1 = exp2f((mo1 - mf1) * L2E);
        float inv0 = 1.f / (l0 * ca0 + lo0 * cb0);
        float inv1 = 1.f / (l1 * ca1 + lo1 * cb1);
        float sa0 = ca0 * inv0, sb0 = cb0 * inv0;
        float sa1 = ca1 * inv1, sb1 = cb1 * inv1;
        #pragma unroll
        for (int t = 0; t < 16; ++t) {
            int col = t * 8 + 2 * qid;
            float2 q0 = *(float2*)&Ps[r_lo * PS_ST + col];
            float2 q1 = *(float2*)&Ps[r_hi * PS_ST + col];
            *(float2*)&g_o[(row0 + r_lo) * 128 + col] =
                make_float2(o[t][0] * sa0 + q0.x * sb0, o[t][1] * sa0 + q0.y * sb0);
            *(float2*)&g_o[(row0 + r_hi) * 128 + col] =
                make_float2(o[t][2] * sa1 + q1.x * sb1, o[t][3] * sa1 + q1.y * sb1);
        }
    }
}

// ---------------------------------------------------------------------------
// Output projection + residual, tf32 MMA 2x-split.
// grid (16 n-tiles of 64, 2 m-tiles of 128, 8 batches), 128 threads.
// y[b,m,hw] = sum_k Ww[m,k]*O[b,k,hw] + Wb[m] + x[b,m,hw]
// ---------------------------------------------------------------------------
__global__ void __launch_bounds__(128) outproj_mma_kernel(
    const float* __restrict__ x,
    const float* __restrict__ Ww, const float* __restrict__ Wb,
    float* __restrict__ y)
{
    __shared__ float Wt[128 * 36];
    __shared__ float Ot[32 * 72];

    const int n0 = blockIdx.x * 64;
    const int m0 = blockIdx.y * 128;
    const int b  = blockIdx.z;
    const float* Ob = g_o + b * 131072;
    const float* xb = x + b * 262144;
    float* yb = y + b * 262144;

    const int tid = threadIdx.x, lane = tid & 31, warp = tid >> 5;
    const int grp = lane >> 2, qid = lane & 3;
    const int m0w = (warp >> 1) * 64, n0w = (warp & 1) * 32;

    float acc[16][4];
    #pragma unroll
    for (int i = 0; i < 16; ++i) { acc[i][0]=0.f; acc[i][1]=0.f; acc[i][2]=0.f; acc[i][3]=0.f; }

    for (int k0 = 0; k0 < 128; k0 += 32) {
        #pragma unroll
        for (int idx = tid; idx < 128 * 8; idx += 128) {
            int m = idx >> 3, k4 = (idx & 7) << 2;
            *(float4*)&Wt[m * 36 + k4] = *(const float4*)&Ww[(m0 + m) * 128 + k0 + k4];
        }
        #pragma unroll
        for (int idx = tid; idx < 32 * 16; idx += 128) {
            int k = idx >> 4, n4 = (idx & 15) << 2;
            *(float4*)&Ot[k * 72 + n4] = *(const float4*)&Ob[(k0 + k) * 1024 + n0 + n4];
        }
        __syncthreads();
        #pragma unroll
        for (int ks = 0; ks < 4; ++ks) {
            const int k = ks * 8;
            unsigned ah[4][4], al[4][4];
            #pragma unroll
            for (int mi = 0; mi < 4; ++mi) {
                int r = m0w + mi * 16 + grp;
                float f0 = Wt[r * 36 + k + qid];
                float f1 = Wt[(r + 8) * 36 + k + qid];
                float f2 = Wt[r * 36 + k + qid + 4];
                float f3 = Wt[(r + 8) * 36 + k + qid + 4];
                ah[mi][0] = tf32_rna(f0); al[mi][0] = tf32_rna(f0 - __uint_as_float(ah[mi][0]));
                ah[mi][1] = tf32_rna(f1); al[mi][1] = tf32_rna(f1 - __uint_as_float(ah[mi][1]));
                ah[mi][2] = tf32_rna(f2); al[mi][2] = tf32_rna(f2 - __uint_as_float(ah[mi][2]));
                ah[mi][3] = tf32_rna(f3); al[mi][3] = tf32_rna(f3 - __uint_as_float(ah[mi][3]));
            }
            #pragma unroll
            for (int ni = 0; ni < 4; ++ni) {
                int c = n0w + ni * 8 + grp;
                unsigned b0 = tf32_rna(Ot[(k + qid) * 72 + c]);
                unsigned b1 = tf32_rna(Ot[(k + qid + 4) * 72 + c]);
                #pragma unroll
                for (int mi = 0; mi < 4; ++mi) {
                    mma_tf32(acc[mi*4+ni], ah[mi][0], ah[mi][1], ah[mi][2], ah[mi][3], b0, b1);
                    mma_tf32(acc[mi*4+ni], al[mi][0], al[mi][1], al[mi][2], al[mi][3], b0, b1);
                }
            }
        }
        __syncthreads();
    }
    #pragma unroll
    for (int mi = 0; mi < 4; ++mi) {
        int m = m0 + m0w + mi * 16 + grp;
        float bv0 = Wb[m], bv1 = Wb[m + 8];
        #pragma unroll
        for (int ni = 0; ni < 4; ++ni) {
            int n = n0 + n0w + ni * 8 + 2 * qid;
            float* a = acc[mi*4+ni];
            float2 x0 = *(const float2*)&xb[m * 1024 + n];
            float2 x1 = *(const float2*)&xb[(m + 8) * 1024 + n];
            *(float2*)&yb[m * 1024 + n] =
                make_float2(a[0] + bv0 + x0.x, a[1] + bv0 + x0.y);
            *(float2*)&yb[(m + 8) * 1024 + n] =
                make_float2(a[2] + bv1 + x1.x, a[3] + bv1 + x1.y);
        }
    }
}

// ---------------------------------------------------------------------------
extern "C" void kernel_launch(void* const* d_in, const int* in_sizes, int n_in,
                              void* d_out, int out_size)
{
    const float* x  = (const float*)d_in[0];
    const float* tw = (const float*)d_in[1];
    const float* tb = (const float*)d_in[2];
    const float* pw = (const float*)d_in[3];
    const float* pb = (const float*)d_in[4];
    const float* gw = (const float*)d_in[5];
    const float* gb = (const float*)d_in[6];
    const float* Ww = (const float*)d_in[7];
    const float* Wb = (const float*)d_in[8];
    float* y = (float*)d_out;

    cudaFuncSetAttribute(attn_mma_kernel,
                         cudaFuncAttributeMaxDynamicSharedMemorySize, ATTN_SMEM);

    proj_mma_kernel<<<dim3(16, 3, 8), 128>>>(x, tw, tb, pw, pb, gw, gb);
    attn_mma_kernel<<<dim3(128), 256, ATTN_SMEM>>>();
    outproj_mma_kernel<<<dim3(16, 2, 8), 128>>>(x, Ww, Wb, y);
}

// round 4
// speedup vs baseline: 5.6722x; 1.2357x over previous
#include <cuda_runtime.h>

#define N_TOT 8192
#define D_DIM 128
#define L2E 1.4426950408889634f
#define NEG_INF (-1.0f/0.0f)

// scratch (allocation-free rule: device globals)
__device__ float g_th[N_TOT * D_DIM];   // theta, flat [B,Cb,HW] == [8192][128]
__device__ float g_ph[N_TOT * D_DIM];   // phi,   flat; viewed as [128][8192]
__device__ float g_gm[N_TOT * D_DIM];   // g,     flat == [8192][128]
__device__ float g_o [N_TOT * D_DIM];   // attn out, flat [B,Cb,HW]

// ---------------------------------------------------------------------------
// helpers
// ---------------------------------------------------------------------------
__device__ __forceinline__ unsigned tf32_rna(float x) {
    unsigned u;
    asm("cvt.rna.tf32.f32 %0, %1;" : "=r"(u) : "f"(x));
    return u;
}

__device__ __forceinline__ void mma_tf32(float c[4],
    unsigned a0, unsigned a1, unsigned a2, unsigned a3,
    unsigned b0, unsigned b1)
{
    asm volatile(
        "mma.sync.aligned.m16n8k8.row.col.f32.tf32.tf32.f32 "
        "{%0,%1,%2,%3}, {%4,%5,%6,%7}, {%8,%9}, {%0,%1,%2,%3};\n"
        : "+f"(c[0]), "+f"(c[1]), "+f"(c[2]), "+f"(c[3])
        : "r"(a0), "r"(a1), "r"(a2), "r"(a3), "r"(b0), "r"(b1));
}

__device__ __forceinline__ void cp16(unsigned smem_addr, const void* gptr) {
    asm volatile("cp.async.cg.shared.global [%0], [%1], 16;\n"
                 :: "r"(smem_addr), "l"(gptr));
}
#define CP_COMMIT() asm volatile("cp.async.commit_group;\n" ::: "memory")
#define CP_WAIT(n)  asm volatile("cp.async.wait_group %0;\n" :: "n"(n) : "memory")

// ---------------------------------------------------------------------------
// Fused projections (theta/phi/g), tf32 MMA 2x-split (kept full precision:
// these errors feed everything downstream and the kernel is only 30us).
// grid (16 n-tiles of 64, 3 projs, 8 batches), 128 threads (4 warps 2m x 2n).
// ---------------------------------------------------------------------------
__global__ void __launch_bounds__(128) proj_mma_kernel(
    const float* __restrict__ x,
    const float* __restrict__ tw, const float* __restrict__ tb,
    const float* __restrict__ pw, const float* __restrict__ pb,
    const float* __restrict__ gw, const float* __restrict__ gb)
{
    __shared__ float Wt[128 * 36];   // A tile [m=128][k=32]
    __shared__ float Xt[32 * 72];    // B tile [k=32][n=64]

    const int n0 = blockIdx.x * 64;
    const int proj = blockIdx.y;
    const int b = blockIdx.z;

    const float* W; const float* bias; float* out;
    if (proj == 0)      { W = tw; bias = tb; out = g_th; }
    else if (proj == 1) { W = pw; bias = pb; out = g_ph; }
    else                { W = gw; bias = gb; out = g_gm; }
    out += b * 131072;
    const float* xb = x + b * 262144;

    const int tid = threadIdx.x, lane = tid & 31, warp = tid >> 5;
    const int grp = lane >> 2, qid = lane & 3;
    const int m0w = (warp >> 1) * 64, n0w = (warp & 1) * 32;

    float acc[16][4];
    #pragma unroll
    for (int i = 0; i < 16; ++i) { acc[i][0]=0.f; acc[i][1]=0.f; acc[i][2]=0.f; acc[i][3]=0.f; }

    for (int k0 = 0; k0 < 256; k0 += 32) {
        #pragma unroll
        for (int idx = tid; idx < 128 * 8; idx += 128) {
            int m = idx >> 3, k4 = (idx & 7) << 2;
            *(float4*)&Wt[m * 36 + k4] = *(const float4*)&W[m * 256 + k0 + k4];
        }
        #pragma unroll
        for (int idx = tid; idx < 32 * 16; idx += 128) {
            int k = idx >> 4, n4 = (idx & 15) << 2;
            *(float4*)&Xt[k * 72 + n4] = *(const float4*)&xb[(k0 + k) * 1024 + n0 + n4];
        }
        __syncthreads();
        #pragma unroll
        for (int ks = 0; ks < 4; ++ks) {
            const int k = ks * 8;
            unsigned ah[4][4], al[4][4];
            #pragma unroll
            for (int mi = 0; mi < 4; ++mi) {
                int r = m0w + mi * 16 + grp;
                float f0 = Wt[r * 36 + k + qid];
                float f1 = Wt[(r + 8) * 36 + k + qid];
                float f2 = Wt[r * 36 + k + qid + 4];
                float f3 = Wt[(r + 8) * 36 + k + qid + 4];
                ah[mi][0] = tf32_rna(f0); al[mi][0] = tf32_rna(f0 - __uint_as_float(ah[mi][0]));
                ah[mi][1] = tf32_rna(f1); al[mi][1] = tf32_rna(f1 - __uint_as_float(ah[mi][1]));
                ah[mi][2] = tf32_rna(f2); al[mi][2] = tf32_rna(f2 - __uint_as_float(ah[mi][2]));
                ah[mi][3] = tf32_rna(f3); al[mi][3] = tf32_rna(f3 - __uint_as_float(ah[mi][3]));
            }
            #pragma unroll
            for (int ni = 0; ni < 4; ++ni) {
                int c = n0w + ni * 8 + grp;
                unsigned b0 = tf32_rna(Xt[(k + qid) * 72 + c]);
                unsigned b1 = tf32_rna(Xt[(k + qid + 4) * 72 + c]);
                #pragma unroll
                for (int mi = 0; mi < 4; ++mi) {
                    mma_tf32(acc[mi*4+ni], ah[mi][0], ah[mi][1], ah[mi][2], ah[mi][3], b0, b1);
                    mma_tf32(acc[mi*4+ni], al[mi][0], al[mi][1], al[mi][2], al[mi][3], b0, b1);
                }
            }
        }
        __syncthreads();
    }
    #pragma unroll
    for (int mi = 0; mi < 4; ++mi) {
        int m = m0w + mi * 16 + grp;
        float bv0 = bias[m], bv1 = bias[m + 8];
        #pragma unroll
        for (int ni = 0; ni < 4; ++ni) {
            int n = n0 + n0w + ni * 8 + 2 * qid;
            float* a = acc[mi*4+ni];
            *(float2*)&out[m * 1024 + n]       = make_float2(a[0] + bv0, a[1] + bv0);
            *(float2*)&out[(m + 8) * 1024 + n] = make_float2(a[2] + bv1, a[3] + bv1);
        }
    }
}

// ---------------------------------------------------------------------------
// Flash attention, tf32 mma.sync (1x tf32 on both GEMMs), cp.async pipelined,
// per-warp-column softmax state. Q pre-converted to tf32 in smem (invariant).
// 128 CTAs x 256 thr; 64 Q rows/CTA; KV tiles of 128.
// ---------------------------------------------------------------------------
#define QS_ST 132
#define KS_ST 136
#define GS_ST 136
#define PS_ST 132
#define ATTN_SMEM ((64*QS_ST + 128*KS_ST + 128*GS_ST + 64*PS_ST + 128) * 4)

__global__ void __launch_bounds__(256, 1) attn_mma_kernel()
{
    extern __shared__ float smf[];
    float* Qs = smf;                       // [64][132]  Qs[r][k] (tf32 bits)
    float* Ks = Qs + 64 * QS_ST;           // [128][136] Ks[k_d][n_kv]
    float* Gs = Ks + 128 * KS_ST;          // [128][136] Gs[kv][d]
    float* Ps = Gs + 128 * GS_ST;          // [64][132]
    float* red_m = Ps + 64 * PS_ST;        // [64]
    float* red_l = red_m + 64;             // [64]

    const int tid  = threadIdx.x;
    const int lane = tid & 31, warp = tid >> 5;
    const int wr = warp >> 1, wc = warp & 1;
    const int grp = lane >> 2, qid = lane & 3;
    const int r_lo = wr * 16 + grp, r_hi = r_lo + 8;
    const int cw0 = wc * 64;
    const int row0 = blockIdx.x * 64;

    const unsigned ks_u = (unsigned)__cvta_generic_to_shared(Ks);
    const unsigned gs_u = (unsigned)__cvta_generic_to_shared(Gs);

    // prologue: start K(0), G(0) streams
    #pragma unroll
    for (int idx = tid; idx < 128 * 32; idx += 256) {
        int k = idx >> 5, n4 = (idx & 31) << 2;
        cp16(ks_u + (k * KS_ST + n4) * 4, &g_ph[k * N_TOT + n4]);
    }
    CP_COMMIT();
    #pragma unroll
    for (int idx = tid; idx < 128 * 32; idx += 256) {
        int kv = idx >> 5, d4 = (idx & 31) << 2;
        cp16(gs_u + (kv * GS_ST + d4) * 4, &g_gm[kv * 128 + d4]);
    }
    CP_COMMIT();

    // Q block (once), pre-rounded to tf32
    #pragma unroll
    for (int idx = tid; idx < 64 * 32; idx += 256) {
        int r = idx >> 5, k4 = (idx & 31) << 2;
        float4 v = *(const float4*)&g_th[(row0 + r) * 128 + k4];
        v.x = __uint_as_float(tf32_rna(v.x));
        v.y = __uint_as_float(tf32_rna(v.y));
        v.z = __uint_as_float(tf32_rna(v.z));
        v.w = __uint_as_float(tf32_rna(v.w));
        *(float4*)&Qs[r * QS_ST + k4] = v;
    }

    float m0 = NEG_INF, m1 = NEG_INF, l0 = 0.f, l1 = 0.f;
    float o[16][4];
    #pragma unroll
    for (int t = 0; t < 16; ++t) { o[t][0]=0.f; o[t][1]=0.f; o[t][2]=0.f; o[t][3]=0.f; }

    for (int it = 0; it < 64; ++it) {
        const int c0 = it * 128;
        CP_WAIT(1);             // K(it) ready (G(it) may still stream)
        __syncthreads();

        // ---- S = Q @ K (1x TF32) ----
        float s[8][4];
        #pragma unroll
        for (int t = 0; t < 8; ++t) { s[t][0]=0.f; s[t][1]=0.f; s[t][2]=0.f; s[t][3]=0.f; }

        #pragma unroll
        for (int ksi = 0; ksi < 16; ++ksi) {
            const int k = ksi * 8;
            unsigned a0 = __float_as_uint(Qs[r_lo * QS_ST + k + qid]);
            unsigned a1 = __float_as_uint(Qs[r_hi * QS_ST + k + qid]);
            unsigned a2 = __float_as_uint(Qs[r_lo * QS_ST + k + qid + 4]);
            unsigned a3 = __float_as_uint(Qs[r_hi * QS_ST + k + qid + 4]);
            #pragma unroll
            for (int t = 0; t < 8; ++t) {
                const float* kp = &Ks[(k + qid) * KS_ST + cw0 + t * 8 + grp];
                unsigned b0 = tf32_rna(kp[0]);
                unsigned b1 = tf32_rna(kp[4 * KS_ST]);
                mma_tf32(s[t], a0, a1, a2, a3, b0, b1);
            }
        }
        __syncthreads();        // everyone done reading Ks

        if (it < 63) {          // stream K(it+1) during softmax + PV
            #pragma unroll
            for (int idx = tid; idx < 128 * 32; idx += 256) {
                int k = idx >> 5, n4 = (idx & 31) << 2;
                cp16(ks_u + (k * KS_ST + n4) * 4, &g_ph[k * N_TOT + c0 + 128 + n4]);
            }
            CP_COMMIT();
        }

        // ---- online softmax (per warp-column state) ----
        float mx0 = NEG_INF, mx1 = NEG_INF;
        #pragma unroll
        for (int t = 0; t < 8; ++t) {
            mx0 = fmaxf(mx0, fmaxf(s[t][0], s[t][1]));
            mx1 = fmaxf(mx1, fmaxf(s[t][2], s[t][3]));
        }
        mx0 = fmaxf(mx0, __shfl_xor_sync(0xffffffffu, mx0, 1));
        mx0 = fmaxf(mx0, __shfl_xor_sync(0xffffffffu, mx0, 2));
        mx1 = fmaxf(mx1, __shfl_xor_sync(0xffffffffu, mx1, 1));
        mx1 = fmaxf(mx1, __shfl_xor_sync(0xffffffffu, mx1, 2));
        float mn0 = fmaxf(m0, mx0), mn1 = fmaxf(m1, mx1);
        float corr0 = exp2f((m0 - mn0) * L2E);
        float corr1 = exp2f((m1 - mn1) * L2E);
        m0 = mn0; m1 = mn1;

        float sum0 = 0.f, sum1 = 0.f;
        #pragma unroll
        for (int t = 0; t < 8; ++t) {
            float p00 = __uint_as_float(tf32_rna(exp2f((s[t][0] - mn0) * L2E)));
            float p01 = __uint_as_float(tf32_rna(exp2f((s[t][1] - mn0) * L2E)));
            float p10 = __uint_as_float(tf32_rna(exp2f((s[t][2] - mn1) * L2E)));
            float p11 = __uint_as_float(tf32_rna(exp2f((s[t][3] - mn1) * L2E)));
            sum0 += p00 + p01;
            sum1 += p10 + p11;
            int col = cw0 + t * 8 + 2 * qid;
            *(float2*)&Ps[r_lo * PS_ST + col] = make_float2(p00, p01);
            *(float2*)&Ps[r_hi * PS_ST + col] = make_float2(p10, p11);
        }
        sum0 += __shfl_xor_sync(0xffffffffu, sum0, 1);
        sum0 += __shfl_xor_sync(0xffffffffu, sum0, 2);
        sum1 += __shfl_xor_sync(0xffffffffu, sum1, 1);
        sum1 += __shfl_xor_sync(0xffffffffu, sum1, 2);
        l0 = l0 * corr0 + sum0;
        l1 = l1 * corr1 + sum1;
        #pragma unroll
        for (int t = 0; t < 16; ++t) {
            o[t][0] *= corr0; o[t][1] *= corr0;
            o[t][2] *= corr1; o[t][3] *= corr1;
        }

        if (it < 63) CP_WAIT(1); else CP_WAIT(0);   // G(it) ready
        __syncthreads();                            // G done + P visible

        // ---- O += P @ G (1x TF32), this warp-col's 64 KV rows ----
        #pragma unroll
        for (int ksi = 0; ksi < 8; ++ksi) {
            const int kv = cw0 + ksi * 8;
            unsigned a0 = __float_as_uint(Ps[r_lo * PS_ST + kv + qid]);
            unsigned a1 = __float_as_uint(Ps[r_hi * PS_ST + kv + qid]);
            unsigned a2 = __float_as_uint(Ps[r_lo * PS_ST + kv + qid + 4]);
            unsigned a3 = __float_as_uint(Ps[r_hi * PS_ST + kv + qid + 4]);
            #pragma unroll
            for (int t = 0; t < 16; ++t) {
                const float* gp = &Gs[(kv + qid) * GS_ST + t * 8 + grp];
                unsigned b0 = tf32_rna(gp[0]);
                unsigned b1 = tf32_rna(gp[4 * GS_ST]);
                mma_tf32(o[t], a0, a1, a2, a3, b0, b1);
            }
        }
        __syncthreads();        // Gs + Ps reads done

        if (it < 63) {          // stream G(it+1) during next S
            #pragma unroll
            for (int idx = tid; idx < 128 * 32; idx += 256) {
                int kv = idx >> 5, d4 = (idx & 31) << 2;
                cp16(gs_u + (kv * GS_ST + d4) * 4, &g_gm[(c0 + 128 + kv) * 128 + d4]);
            }
            CP_COMMIT();
        }
    }

    // ---- epilogue: merge the two warp-column partials ----
    if (wc == 1) {
        if (qid == 0) {
            red_m[r_lo] = m0; red_l[r_lo] = l0;
            red_m[r_hi] = m1; red_l[r_hi] = l1;
        }
        #pragma unroll
        for (int t = 0; t < 16; ++t) {
            int col = t * 8 + 2 * qid;
            *(float2*)&Ps[r_lo * PS_ST + col] = make_float2(o[t][0], o[t][1]);
            *(float2*)&Ps[r_hi * PS_ST + col] = make_float2(o[t][2], o[t][3]);
        }
    }
    __syncthreads();
    if (wc == 0) {
        float mo0 = red_m[r_lo], lo0 = red_l[r_lo];
        float mo1 = red_m[r_hi], lo1 = red_l[r_hi];
        float mf0 = fmaxf(m0, mo0), mf1 = fmaxf(m1, mo1);
        float ca0 = exp2f((m0 - mf0) * L2E), cb0 = exp2f((mo0 - mf0) * L2E);
        float ca1 = exp2f((m1 - mf1) * L2E), cb1 = exp2f((mo1 - mf1) * L2E);
        float inv0 = 1.f / (l0 * ca0 + lo0 * cb0);
        float inv1 = 1.f / (l1 * ca1 + lo1 * cb1);
        float sa0 = ca0 * inv0, sb0 = cb0 * inv0;
        float sa1 = ca1 * inv1, sb1 = cb1 * inv1;
        #pragma unroll
        for (int t = 0; t < 16; ++t) {
            int col = t * 8 + 2 * qid;
            float2 q0 = *(float2*)&Ps[r_lo * PS_ST + col];
            float2 q1 = *(float2*)&Ps[r_hi * PS_ST + col];
            *(float2*)&g_o[(row0 + r_lo) * 128 + col] =
                make_float2(o[t][0] * sa0 + q0.x * sb0, o[t][1] * sa0 + q0.y * sb0);
            *(float2*)&g_o[(row0 + r_hi) * 128 + col] =
                make_float2(o[t][2] * sa1 + q1.x * sb1, o[t][3] * sa1 + q1.y * sb1);
        }
    }
}

// ---------------------------------------------------------------------------
// Output projection + residual, tf32 MMA 2x-split.
// ---------------------------------------------------------------------------
__global__ void __launch_bounds__(128) outproj_mma_kernel(
    const float* __restrict__ x,
    const float* __restrict__ Ww, const float* __restrict__ Wb,
    float* __restrict__ y)
{
    __shared__ float Wt[128 * 36];
    __shared__ float Ot[32 * 72];

    const int n0 = blockIdx.x * 64;
    const int m0 = blockIdx.y * 128;
    const int b  = blockIdx.z;
    const float* Ob = g_o + b * 131072;
    const float* xb = x + b * 262144;
    float* yb = y + b * 262144;

    const int tid = threadIdx.x, lane = tid & 31, warp = tid >> 5;
    const int grp = lane >> 2, qid = lane & 3;
    const int m0w = (warp >> 1) * 64, n0w = (warp & 1) * 32;

    float acc[16][4];
    #pragma unroll
    for (int i = 0; i < 16; ++i) { acc[i][0]=0.f; acc[i][1]=0.f; acc[i][2]=0.f; acc[i][3]=0.f; }

    for (int k0 = 0; k0 < 128; k0 += 32) {
        #pragma unroll
        for (int idx = tid; idx < 128 * 8; idx += 128) {
            int m = idx >> 3, k4 = (idx & 7) << 2;
            *(float4*)&Wt[m * 36 + k4] = *(const float4*)&Ww[(m0 + m) * 128 + k0 + k4];
        }
        #pragma unroll
        for (int idx = tid; idx < 32 * 16; idx += 128) {
            int k = idx >> 4, n4 = (idx & 15) << 2;
            *(float4*)&Ot[k * 72 + n4] = *(const float4*)&Ob[(k0 + k) * 1024 + n0 + n4];
        }
        __syncthreads();
        #pragma unroll
        for (int ks = 0; ks < 4; ++ks) {
            const int k = ks * 8;
            unsigned ah[4][4], al[4][4];
            #pragma unroll
            for (int mi = 0; mi < 4; ++mi) {
                int r = m0w + mi * 16 + grp;
                float f0 = Wt[r * 36 + k + qid];
                float f1 = Wt[(r + 8) * 36 + k + qid];
                float f2 = Wt[r * 36 + k + qid + 4];
                float f3 = Wt[(r + 8) * 36 + k + qid + 4];
                ah[mi][0] = tf32_rna(f0); al[mi][0] = tf32_rna(f0 - __uint_as_float(ah[mi][0]));
                ah[mi][1] = tf32_rna(f1); al[mi][1] = tf32_rna(f1 - __uint_as_float(ah[mi][1]));
                ah[mi][2] = tf32_rna(f2); al[mi][2] = tf32_rna(f2 - __uint_as_float(ah[mi][2]));
                ah[mi][3] = tf32_rna(f3); al[mi][3] = tf32_rna(f3 - __uint_as_float(ah[mi][3]));
            }
            #pragma unroll
            for (int ni = 0; ni < 4; ++ni) {
                int c = n0w + ni * 8 + grp;
                unsigned b0 = tf32_rna(Ot[(k + qid) * 72 + c]);
                unsigned b1 = tf32_rna(Ot[(k + qid + 4) * 72 + c]);
                #pragma unroll
                for (int mi = 0; mi < 4; ++mi) {
                    mma_tf32(acc[mi*4+ni], ah[mi][0], ah[mi][1], ah[mi][2], ah[mi][3], b0, b1);
                    mma_tf32(acc[mi*4+ni], al[mi][0], al[mi][1], al[mi][2], al[mi][3], b0, b1);
                }
            }
        }
        __syncthreads();
    }
    #pragma unroll
    for (int mi = 0; mi < 4; ++mi) {
        int m = m0 + m0w + mi * 16 + grp;
        float bv0 = Wb[m], bv1 = Wb[m + 8];
        #pragma unroll
        for (int ni = 0; ni < 4; ++ni) {
            int n = n0 + n0w + ni * 8 + 2 * qid;
            float* a = acc[mi*4+ni];
            float2 x0 = *(const float2*)&xb[m * 1024 + n];
            float2 x1 = *(const float2*)&xb[(m + 8) * 1024 + n];
            *(float2*)&yb[m * 1024 + n] =
                make_float2(a[0] + bv0 + x0.x, a[1] + bv0 + x0.y);
            *(float2*)&yb[(m + 8) * 1024 + n] =
                make_float2(a[2] + bv1 + x1.x, a[3] + bv1 + x1.y);
        }
    }
}

// ---------------------------------------------------------------------------
extern "C" void kernel_launch(void* const* d_in, const int* in_sizes, int n_in,
                              void* d_out, int out_size)
{
    const float* x  = (const float*)d_in[0];
    const float* tw = (const float*)d_in[1];
    const float* tb = (const float*)d_in[2];
    const float* pw = (const float*)d_in[3];
    const float* pb = (const float*)d_in[4];
    const float* gw = (const float*)d_in[5];
    const float* gb = (const float*)d_in[6];
    const float* Ww = (const float*)d_in[7];
    const float* Wb = (const float*)d_in[8];
    float* y = (float*)d_out;

    cudaFuncSetAttribute(attn_mma_kernel,
                         cudaFuncAttributeMaxDynamicSharedMemorySize, ATTN_SMEM);

    proj_mma_kernel<<<dim3(16, 3, 8), 128>>>(x, tw, tb, pw, pb, gw, gb);
    attn_mma_kernel<<<dim3(128), 256, ATTN_SMEM>>>();
    outproj_mma_kernel<<<dim3(16, 2, 8), 128>>>(x, Ww, Wb, y);
}

// round 5
// speedup vs baseline: 6.2194x; 1.0965x over previous
#include <cuda_runtime.h>

#define N_TOT 8192
#define D_DIM 128
#define L2E 1.4426950408889634f
#define NEG_INF (-1.0f/0.0f)

// scratch (allocation-free rule: device globals)
__device__ float g_th[N_TOT * D_DIM];   // theta (tf32-rounded), [8192][128]
__device__ float g_ph[N_TOT * D_DIM];   // phi   (tf32-rounded), viewed [128][8192]
__device__ float g_gm[N_TOT * D_DIM];   // g     (tf32-rounded), [8192][128]
__device__ float g_o [N_TOT * D_DIM];   // attn out (fp32), [8192][128]

// ---------------------------------------------------------------------------
// helpers
// ---------------------------------------------------------------------------
__device__ __forceinline__ unsigned tf32_rna(float x) {
    unsigned u;
    asm("cvt.rna.tf32.f32 %0, %1;" : "=r"(u) : "f"(x));
    return u;
}

__device__ __forceinline__ float ex2(float x) {
    float y;
    asm("ex2.approx.f32 %0, %1;" : "=f"(y) : "f"(x));
    return y;
}

__device__ __forceinline__ void mma_tf32(float c[4],
    unsigned a0, unsigned a1, unsigned a2, unsigned a3,
    unsigned b0, unsigned b1)
{
    asm volatile(
        "mma.sync.aligned.m16n8k8.row.col.f32.tf32.tf32.f32 "
        "{%0,%1,%2,%3}, {%4,%5,%6,%7}, {%8,%9}, {%0,%1,%2,%3};\n"
        : "+f"(c[0]), "+f"(c[1]), "+f"(c[2]), "+f"(c[3])
        : "r"(a0), "r"(a1), "r"(a2), "r"(a3), "r"(b0), "r"(b1));
}

__device__ __forceinline__ void cp16(unsigned smem_addr, const void* gptr) {
    asm volatile("cp.async.cg.shared.global [%0], [%1], 16;\n"
                 :: "r"(smem_addr), "l"(gptr));
}
#define CP_COMMIT() asm volatile("cp.async.commit_group;\n" ::: "memory")
#define CP_WAIT(n)  asm volatile("cp.async.wait_group %0;\n" :: "n"(n) : "memory")

// ---------------------------------------------------------------------------
// Fused projections (theta/phi/g), tf32 MMA 2x-split, outputs rounded to tf32
// so the attention kernel consumes raw bits (no cvt in its hot loop).
// grid (16 n-tiles of 64, 3 projs, 8 batches), 128 threads (4 warps 2m x 2n).
// ---------------------------------------------------------------------------
__global__ void __launch_bounds__(128) proj_mma_kernel(
    const float* __restrict__ x,
    const float* __restrict__ tw, const float* __restrict__ tb,
    const float* __restrict__ pw, const float* __restrict__ pb,
    const float* __restrict__ gw, const float* __restrict__ gb)
{
    __shared__ float Wt[128 * 36];   // A tile [m=128][k=32]
    __shared__ float Xt[32 * 72];    // B tile [k=32][n=64]

    const int n0 = blockIdx.x * 64;
    const int proj = blockIdx.y;
    const int b = blockIdx.z;

    const float* W; const float* bias; float* out;
    if (proj == 0)      { W = tw; bias = tb; out = g_th; }
    else if (proj == 1) { W = pw; bias = pb; out = g_ph; }
    else                { W = gw; bias = gb; out = g_gm; }
    out += b * 131072;
    const float* xb = x + b * 262144;

    const int tid = threadIdx.x, lane = tid & 31, warp = tid >> 5;
    const int grp = lane >> 2, qid = lane & 3;
    const int m0w = (warp >> 1) * 64, n0w = (warp & 1) * 32;

    float acc[16][4];
    #pragma unroll
    for (int i = 0; i < 16; ++i) { acc[i][0]=0.f; acc[i][1]=0.f; acc[i][2]=0.f; acc[i][3]=0.f; }

    for (int k0 = 0; k0 < 256; k0 += 32) {
        #pragma unroll
        for (int idx = tid; idx < 128 * 8; idx += 128) {
            int m = idx >> 3, k4 = (idx & 7) << 2;
            *(float4*)&Wt[m * 36 + k4] = *(const float4*)&W[m * 256 + k0 + k4];
        }
        #pragma unroll
        for (int idx = tid; idx < 32 * 16; idx += 128) {
            int k = idx >> 4, n4 = (idx & 15) << 2;
            *(float4*)&Xt[k * 72 + n4] = *(const float4*)&xb[(k0 + k) * 1024 + n0 + n4];
        }
        __syncthreads();
        #pragma unroll
        for (int ks = 0; ks < 4; ++ks) {
            const int k = ks * 8;
            unsigned ah[4][4], al[4][4];
            #pragma unroll
            for (int mi = 0; mi < 4; ++mi) {
                int r = m0w + mi * 16 + grp;
                float f0 = Wt[r * 36 + k + qid];
                float f1 = Wt[(r + 8) * 36 + k + qid];
                float f2 = Wt[r * 36 + k + qid + 4];
                float f3 = Wt[(r + 8) * 36 + k + qid + 4];
                ah[mi][0] = tf32_rna(f0); al[mi][0] = tf32_rna(f0 - __uint_as_float(ah[mi][0]));
                ah[mi][1] = tf32_rna(f1); al[mi][1] = tf32_rna(f1 - __uint_as_float(ah[mi][1]));
                ah[mi][2] = tf32_rna(f2); al[mi][2] = tf32_rna(f2 - __uint_as_float(ah[mi][2]));
                ah[mi][3] = tf32_rna(f3); al[mi][3] = tf32_rna(f3 - __uint_as_float(ah[mi][3]));
            }
            #pragma unroll
            for (int ni = 0; ni < 4; ++ni) {
                int c = n0w + ni * 8 + grp;
                unsigned b0 = tf32_rna(Xt[(k + qid) * 72 + c]);
                unsigned b1 = tf32_rna(Xt[(k + qid + 4) * 72 + c]);
                #pragma unroll
                for (int mi = 0; mi < 4; ++mi) {
                    mma_tf32(acc[mi*4+ni], ah[mi][0], ah[mi][1], ah[mi][2], ah[mi][3], b0, b1);
                    mma_tf32(acc[mi*4+ni], al[mi][0], al[mi][1], al[mi][2], al[mi][3], b0, b1);
                }
            }
        }
        __syncthreads();
    }
    #pragma unroll
    for (int mi = 0; mi < 4; ++mi) {
        int m = m0w + mi * 16 + grp;
        float bv0 = bias[m], bv1 = bias[m + 8];
        #pragma unroll
        for (int ni = 0; ni < 4; ++ni) {
            int n = n0 + n0w + ni * 8 + 2 * qid;
            float* a = acc[mi*4+ni];
            *(float2*)&out[m * 1024 + n] = make_float2(
                __uint_as_float(tf32_rna(a[0] + bv0)),
                __uint_as_float(tf32_rna(a[1] + bv0)));
            *(float2*)&out[(m + 8) * 1024 + n] = make_float2(
                __uint_as_float(tf32_rna(a[2] + bv1)),
                __uint_as_float(tf32_rna(a[3] + bv1)));
        }
    }
}

// ---------------------------------------------------------------------------
// Flash attention, tf32 mma.sync, cp.async pipelined, per-warp-col softmax.
// Inputs pre-rounded to tf32 -> zero cvt in the hot loop.
// Q fragments held in registers (invariant across all 64 KV iterations).
// 128 CTAs x 256 thr; 64 Q rows/CTA; KV tiles of 128.
// ---------------------------------------------------------------------------
#define KS_ST 136
#define GS_ST 136
#define PS_ST 132
#define ATTN_SMEM ((128*KS_ST + 128*GS_ST + 64*PS_ST + 128) * 4)

__global__ void __launch_bounds__(256, 1) attn_mma_kernel()
{
    extern __shared__ float smf[];
    float* Ks = smf;                       // [128][136] Ks[k_d][n_kv]
    float* Gs = Ks + 128 * KS_ST;          // [128][136] Gs[kv][d]
    float* Ps = Gs + 128 * GS_ST;          // [64][132]  P tile (also Q staging)
    float* red_m = Ps + 64 * PS_ST;        // [64]
    float* red_l = red_m + 64;             // [64]

    const int tid  = threadIdx.x;
    const int lane = tid & 31, warp = tid >> 5;
    const int wr = warp >> 1, wc = warp & 1;
    const int grp = lane >> 2, qid = lane & 3;
    const int r_lo = wr * 16 + grp, r_hi = r_lo + 8;
    const int cw0 = wc * 64;
    const int row0 = blockIdx.x * 64;

    const unsigned ks_u = (unsigned)__cvta_generic_to_shared(Ks);
    const unsigned gs_u = (unsigned)__cvta_generic_to_shared(Gs);

    // prologue: start K(0), G(0) streams
    #pragma unroll
    for (int idx = tid; idx < 128 * 32; idx += 256) {
        int k = idx >> 5, n4 = (idx & 31) << 2;
        cp16(ks_u + (k * KS_ST + n4) * 4, &g_ph[k * N_TOT + n4]);
    }
    CP_COMMIT();
    #pragma unroll
    for (int idx = tid; idx < 128 * 32; idx += 256) {
        int kv = idx >> 5, d4 = (idx & 31) << 2;
        cp16(gs_u + (kv * GS_ST + d4) * 4, &g_gm[kv * 128 + d4]);
    }
    CP_COMMIT();

    // stage Q through Ps, pick up fragments into registers (already tf32)
    #pragma unroll
    for (int idx = tid; idx < 64 * 32; idx += 256) {
        int r = idx >> 5, k4 = (idx & 31) << 2;
        *(float4*)&Ps[r * PS_ST + k4] = *(const float4*)&g_th[(row0 + r) * 128 + k4];
    }
    __syncthreads();
    unsigned qa[16][4];
    #pragma unroll
    for (int ksi = 0; ksi < 16; ++ksi) {
        const int k = ksi * 8;
        qa[ksi][0] = __float_as_uint(Ps[r_lo * PS_ST + k + qid]);
        qa[ksi][1] = __float_as_uint(Ps[r_hi * PS_ST + k + qid]);
        qa[ksi][2] = __float_as_uint(Ps[r_lo * PS_ST + k + qid + 4]);
        qa[ksi][3] = __float_as_uint(Ps[r_hi * PS_ST + k + qid + 4]);
    }

    float m0 = NEG_INF, m1 = NEG_INF, l0 = 0.f, l1 = 0.f;
    float o[16][4];
    #pragma unroll
    for (int t = 0; t < 16; ++t) { o[t][0]=0.f; o[t][1]=0.f; o[t][2]=0.f; o[t][3]=0.f; }

    for (int it = 0; it < 64; ++it) {
        const int c0 = it * 128;
        CP_WAIT(1);             // K(it) ready (G(it) may still stream)
        __syncthreads();

        // ---- S = Q @ K (1x TF32, zero cvt) ----
        float s[8][4];
        #pragma unroll
        for (int t = 0; t < 8; ++t) { s[t][0]=0.f; s[t][1]=0.f; s[t][2]=0.f; s[t][3]=0.f; }

        #pragma unroll
        for (int ksi = 0; ksi < 16; ++ksi) {
            const int k = ksi * 8;
            #pragma unroll
            for (int t = 0; t < 8; ++t) {
                const unsigned* kp =
                    (const unsigned*)&Ks[(k + qid) * KS_ST + cw0 + t * 8 + grp];
                mma_tf32(s[t], qa[ksi][0], qa[ksi][1], qa[ksi][2], qa[ksi][3],
                         kp[0], kp[4 * KS_ST]);
            }
        }
        __syncthreads();        // everyone done reading Ks

        if (it < 63) {          // stream K(it+1) during softmax + PV
            #pragma unroll
            for (int idx = tid; idx < 128 * 32; idx += 256) {
                int k = idx >> 5, n4 = (idx & 31) << 2;
                cp16(ks_u + (k * KS_ST + n4) * 4, &g_ph[k * N_TOT + c0 + 128 + n4]);
            }
            CP_COMMIT();
        }

        // ---- online softmax (per warp-column state) ----
        float mx0 = NEG_INF, mx1 = NEG_INF;
        #pragma unroll
        for (int t = 0; t < 8; ++t) {
            mx0 = fmaxf(mx0, fmaxf(s[t][0], s[t][1]));
            mx1 = fmaxf(mx1, fmaxf(s[t][2], s[t][3]));
        }
        mx0 = fmaxf(mx0, __shfl_xor_sync(0xffffffffu, mx0, 1));
        mx0 = fmaxf(mx0, __shfl_xor_sync(0xffffffffu, mx0, 2));
        mx1 = fmaxf(mx1, __shfl_xor_sync(0xffffffffu, mx1, 1));
        mx1 = fmaxf(mx1, __shfl_xor_sync(0xffffffffu, mx1, 2));
        float mn0 = fmaxf(m0, mx0), mn1 = fmaxf(m1, mx1);
        float corr0 = ex2((m0 - mn0) * L2E);
        float corr1 = ex2((m1 - mn1) * L2E);
        m0 = mn0; m1 = mn1;

        float sum0 = 0.f, sum1 = 0.f;
        #pragma unroll
        for (int t = 0; t < 8; ++t) {
            float p00 = __uint_as_float(tf32_rna(ex2((s[t][0] - mn0) * L2E)));
            float p01 = __uint_as_float(tf32_rna(ex2((s[t][1] - mn0) * L2E)));
            float p10 = __uint_as_float(tf32_rna(ex2((s[t][2] - mn1) * L2E)));
            float p11 = __uint_as_float(tf32_rna(ex2((s[t][3] - mn1) * L2E)));
            sum0 += p00 + p01;
            sum1 += p10 + p11;
            int col = cw0 + t * 8 + 2 * qid;
            *(float2*)&Ps[r_lo * PS_ST + col] = make_float2(p00, p01);
            *(float2*)&Ps[r_hi * PS_ST + col] = make_float2(p10, p11);
        }
        sum0 += __shfl_xor_sync(0xffffffffu, sum0, 1);
        sum0 += __shfl_xor_sync(0xffffffffu, sum0, 2);
        sum1 += __shfl_xor_sync(0xffffffffu, sum1, 1);
        sum1 += __shfl_xor_sync(0xffffffffu, sum1, 2);
        l0 = l0 * corr0 + sum0;
        l1 = l1 * corr1 + sum1;
        #pragma unroll
        for (int t = 0; t < 16; ++t) {
            o[t][0] *= corr0; o[t][1] *= corr0;
            o[t][2] *= corr1; o[t][3] *= corr1;
        }

        if (it < 63) CP_WAIT(1); else CP_WAIT(0);   // G(it) ready
        __syncthreads();                            // G done + P visible

        // ---- O += P @ G (1x TF32, zero cvt), this warp-col's 64 KV rows ----
        #pragma unroll
        for (int ksi = 0; ksi < 8; ++ksi) {
            const int kv = cw0 + ksi * 8;
            unsigned a0 = __float_as_uint(Ps[r_lo * PS_ST + kv + qid]);
            unsigned a1 = __float_as_uint(Ps[r_hi * PS_ST + kv + qid]);
            unsigned a2 = __float_as_uint(Ps[r_lo * PS_ST + kv + qid + 4]);
            unsigned a3 = __float_as_uint(Ps[r_hi * PS_ST + kv + qid + 4]);
            #pragma unroll
            for (int t = 0; t < 16; ++t) {
                const unsigned* gp =
                    (const unsigned*)&Gs[(kv + qid) * GS_ST + t * 8 + grp];
                mma_tf32(o[t], a0, a1, a2, a3, gp[0], gp[4 * GS_ST]);
            }
        }
        __syncthreads();        // Gs + Ps reads done

        if (it < 63) {          // stream G(it+1) during next S
            #pragma unroll
            for (int idx = tid; idx < 128 * 32; idx += 256) {
                int kv = idx >> 5, d4 = (idx & 31) << 2;
                cp16(gs_u + (kv * GS_ST + d4) * 4, &g_gm[(c0 + 128 + kv) * 128 + d4]);
            }
            CP_COMMIT();
        }
    }

    // ---- epilogue: merge the two warp-column partials ----
    if (wc == 1) {
        if (qid == 0) {
            red_m[r_lo] = m0; red_l[r_lo] = l0;
            red_m[r_hi] = m1; red_l[r_hi] = l1;
        }
        #pragma unroll
        for (int t = 0; t < 16; ++t) {
            int col = t * 8 + 2 * qid;
            *(float2*)&Ps[r_lo * PS_ST + col] = make_float2(o[t][0], o[t][1]);
            *(float2*)&Ps[r_hi * PS_ST + col] = make_float2(o[t][2], o[t][3]);
        }
    }
    __syncthreads();
    if (wc == 0) {
        float mo0 = red_m[r_lo], lo0 = red_l[r_lo];
        float mo1 = red_m[r_hi], lo1 = red_l[r_hi];
        float mf0 = fmaxf(m0, mo0), mf1 = fmaxf(m1, mo1);
        float ca0 = ex2((m0 - mf0) * L2E), cb0 = ex2((mo0 - mf0) * L2E);
        float ca1 = ex2((m1 - mf1) * L2E), cb1 = ex2((mo1 - mf1) * L2E);
        float inv0 = 1.f / (l0 * ca0 + lo0 * cb0);
        float inv1 = 1.f / (l1 * ca1 + lo1 * cb1);
        float sa0 = ca0 * inv0, sb0 = cb0 * inv0;
        float sa1 = ca1 * inv1, sb1 = cb1 * inv1;
        #pragma unroll
        for (int t = 0; t < 16; ++t) {
            int col = t * 8 + 2 * qid;
            float2 q0 = *(float2*)&Ps[r_lo * PS_ST + col];
            float2 q1 = *(float2*)&Ps[r_hi * PS_ST + col];
            *(float2*)&g_o[(row0 + r_lo) * 128 + col] =
                make_float2(o[t][0] * sa0 + q0.x * sb0, o[t][1] * sa0 + q0.y * sb0);
            *(float2*)&g_o[(row0 + r_hi) * 128 + col] =
                make_float2(o[t][2] * sa1 + q1.x * sb1, o[t][3] * sa1 + q1.y * sb1);
        }
    }
}

// ---------------------------------------------------------------------------
// Output projection + residual, tf32 MMA 2x-split.
// ---------------------------------------------------------------------------
__global__ void __launch_bounds__(128) outproj_mma_kernel(
    const float* __restrict__ x,
    const float* __restrict__ Ww, const float* __restrict__ Wb,
    float* __restrict__ y)
{
    __shared__ float Wt[128 * 36];
    __shared__ float Ot[32 * 72];

    const int n0 = blockIdx.x * 64;
    const int m0 = blockIdx.y * 128;
    const int b  = blockIdx.z;
    const float* Ob = g_o + b * 131072;
    const float* xb = x + b * 262144;
    float* yb = y + b * 262144;

    const int tid = threadIdx.x, lane = tid & 31, warp = tid >> 5;
    const int grp = lane >> 2, qid = lane & 3;
    const int m0w = (warp >> 1) * 64, n0w = (warp & 1) * 32;

    float acc[16][4];
    #pragma unroll
    for (int i = 0; i < 16; ++i) { acc[i][0]=0.f; acc[i][1]=0.f; acc[i][2]=0.f; acc[i][3]=0.f; }

    for (int k0 = 0; k0 < 128; k0 += 32) {
        #pragma unroll
        for (int idx = tid; idx < 128 * 8; idx += 128) {
            int m = idx >> 3, k4 = (idx & 7) << 2;
            *(float4*)&Wt[m * 36 + k4] = *(const float4*)&Ww[(m0 + m) * 128 + k0 + k4];
        }
        #pragma unroll
        for (int idx = tid; idx < 32 * 16; idx += 128) {
            int k = idx >> 4, n4 = (idx & 15) << 2;
            *(float4*)&Ot[k * 72 + n4] = *(const float4*)&Ob[(k0 + k) * 1024 + n0 + n4];
        }
        __syncthreads();
        #pragma unroll
        for (int ks = 0; ks < 4; ++ks) {
            const int k = ks * 8;
            unsigned ah[4][4], al[4][4];
            #pragma unroll
            for (int mi = 0; mi < 4; ++mi) {
                int r = m0w + mi * 16 + grp;
                float f0 = Wt[r * 36 + k + qid];
                float f1 = Wt[(r + 8) * 36 + k + qid];
                float f2 = Wt[r * 36 + k + qid + 4];
                float f3 = Wt[(r + 8) * 36 + k + qid + 4];
                ah[mi][0] = tf32_rna(f0); al[mi][0] = tf32_rna(f0 - __uint_as_float(ah[mi][0]));
                ah[mi][1] = tf32_rna(f1); al[mi][1] = tf32_rna(f1 - __uint_as_float(ah[mi][1]));
                ah[mi][2] = tf32_rna(f2); al[mi][2] = tf32_rna(f2 - __uint_as_float(ah[mi][2]));
                ah[mi][3] = tf32_rna(f3); al[mi][3] = tf32_rna(f3 - __uint_as_float(ah[mi][3]));
            }
            #pragma unroll
            for (int ni = 0; ni < 4; ++ni) {
                int c = n0w + ni * 8 + grp;
                unsigned b0 = tf32_rna(Ot[(k + qid) * 72 + c]);
                unsigned b1 = tf32_rna(Ot[(k + qid + 4) * 72 + c]);
                #pragma unroll
                for (int mi = 0; mi < 4; ++mi) {
                    mma_tf32(acc[mi*4+ni], ah[mi][0], ah[mi][1], ah[mi][2], ah[mi][3], b0, b1);
                    mma_tf32(acc[mi*4+ni], al[mi][0], al[mi][1], al[mi][2], al[mi][3], b0, b1);
                }
            }
        }
        __syncthreads();
    }
    #pragma unroll
    for (int mi = 0; mi < 4; ++mi) {
        int m = m0 + m0w + mi * 16 + grp;
        float bv0 = Wb[m], bv1 = Wb[m + 8];
        #pragma unroll
        for (int ni = 0; ni < 4; ++ni) {
            int n = n0 + n0w + ni * 8 + 2 * qid;
            float* a = acc[mi*4+ni];
            float2 x0 = *(const float2*)&xb[m * 1024 + n];
            float2 x1 = *(const float2*)&xb[(m + 8) * 1024 + n];
            *(float2*)&yb[m * 1024 + n] =
                make_float2(a[0] + bv0 + x0.x, a[1] + bv0 + x0.y);
            *(float2*)&yb[(m + 8) * 1024 + n] =
                make_float2(a[2] + bv1 + x1.x, a[3] + bv1 + x1.y);
        }
    }
}

// ---------------------------------------------------------------------------
extern "C" void kernel_launch(void* const* d_in, const int* in_sizes, int n_in,
                              void* d_out, int out_size)
{
    const float* x  = (const float*)d_in[0];
    const float* tw = (const float*)d_in[1];
    const float* tb = (const float*)d_in[2];
    const float* pw = (const float*)d_in[3];
    const float* pb = (const float*)d_in[4];
    const float* gw = (const float*)d_in[5];
    const float* gb = (const float*)d_in[6];
    const float* Ww = (const float*)d_in[7];
    const float* Wb = (const float*)d_in[8];
    float* y = (float*)d_out;

    cudaFuncSetAttribute(attn_mma_kernel,
                         cudaFuncAttributeMaxDynamicSharedMemorySize, ATTN_SMEM);

    proj_mma_kernel<<<dim3(16, 3, 8), 128>>>(x, tw, tb, pw, pb, gw, gb);
    attn_mma_kernel<<<dim3(128), 256, ATTN_SMEM>>>();
    outproj_mma_kernel<<<dim3(16, 2, 8), 128>>>(x, Ww, Wb, y);
}

// round 6
// speedup vs baseline: 9.4108x; 1.5131x over previous
#include <cuda_runtime.h>
#include <cuda_fp16.h>

#define N_TOT 8192
#define D_DIM 128
#define L2E 1.4426950408889634f
#define NEG_INF (-1.0f/0.0f)

// scratch (allocation-free rule: device globals)
__device__ __half g_th16[N_TOT * D_DIM];   // theta fp16, [8192][128]
__device__ __half g_ph16[N_TOT * D_DIM];   // phi   fp16, viewed [128][8192]
__device__ __half g_gm16[N_TOT * D_DIM];   // g     fp16, [8192][128]
__device__ float  g_o   [N_TOT * D_DIM];   // attn out fp32, [8192][128]

// ---------------------------------------------------------------------------
// helpers
// ---------------------------------------------------------------------------
__device__ __forceinline__ unsigned tf32_rna(float x) {
    unsigned u;
    asm("cvt.rna.tf32.f32 %0, %1;" : "=r"(u) : "f"(x));
    return u;
}
__device__ __forceinline__ float ex2(float x) {
    float y;
    asm("ex2.approx.f32 %0, %1;" : "=f"(y) : "f"(x));
    return y;
}
__device__ __forceinline__ void mma_tf32(float c[4],
    unsigned a0, unsigned a1, unsigned a2, unsigned a3,
    unsigned b0, unsigned b1)
{
    asm volatile(
        "mma.sync.aligned.m16n8k8.row.col.f32.tf32.tf32.f32 "
        "{%0,%1,%2,%3}, {%4,%5,%6,%7}, {%8,%9}, {%0,%1,%2,%3};\n"
        : "+f"(c[0]), "+f"(c[1]), "+f"(c[2]), "+f"(c[3])
        : "r"(a0), "r"(a1), "r"(a2), "r"(a3), "r"(b0), "r"(b1));
}
__device__ __forceinline__ void mma_f16(float c[4],
    unsigned a0, unsigned a1, unsigned a2, unsigned a3,
    unsigned b0, unsigned b1)
{
    asm volatile(
        "mma.sync.aligned.m16n8k16.row.col.f32.f16.f16.f32 "
        "{%0,%1,%2,%3}, {%4,%5,%6,%7}, {%8,%9}, {%0,%1,%2,%3};\n"
        : "+f"(c[0]), "+f"(c[1]), "+f"(c[2]), "+f"(c[3])
        : "r"(a0), "r"(a1), "r"(a2), "r"(a3), "r"(b0), "r"(b1));
}
__device__ __forceinline__ void ldsm_x4(unsigned& r0, unsigned& r1,
                                        unsigned& r2, unsigned& r3, unsigned addr)
{
    asm volatile("ldmatrix.sync.aligned.m8n8.x4.shared.b16 {%0,%1,%2,%3}, [%4];"
                 : "=r"(r0), "=r"(r1), "=r"(r2), "=r"(r3) : "r"(addr));
}
__device__ __forceinline__ void ldsm_x2_t(unsigned& r0, unsigned& r1, unsigned addr)
{
    asm volatile("ldmatrix.sync.aligned.m8n8.x2.trans.shared.b16 {%0,%1}, [%2];"
                 : "=r"(r0), "=r"(r1) : "r"(addr));
}
__device__ __forceinline__ unsigned h2u(__half2 h) {
    return *reinterpret_cast<unsigned*>(&h);
}
__device__ __forceinline__ void cp16(unsigned smem_addr, const void* gptr) {
    asm volatile("cp.async.cg.shared.global [%0], [%1], 16;\n"
                 :: "r"(smem_addr), "l"(gptr));
}
#define CP_COMMIT() asm volatile("cp.async.commit_group;\n" ::: "memory")
#define CP_WAIT(n)  asm volatile("cp.async.wait_group %0;\n" :: "n"(n) : "memory")

// ---------------------------------------------------------------------------
// Fused projections (theta/phi/g), tf32 MMA 2x-split internally, fp16 output.
// grid (16 n-tiles of 64, 3 projs, 8 batches), 128 threads.
// ---------------------------------------------------------------------------
__global__ void __launch_bounds__(128) proj_mma_kernel(
    const float* __restrict__ x,
    const float* __restrict__ tw, const float* __restrict__ tb,
    const float* __restrict__ pw, const float* __restrict__ pb,
    const float* __restrict__ gw, const float* __restrict__ gb)
{
    __shared__ float Wt[128 * 36];
    __shared__ float Xt[32 * 72];

    const int n0 = blockIdx.x * 64;
    const int proj = blockIdx.y;
    const int b = blockIdx.z;

    const float* W; const float* bias; __half* out;
    if (proj == 0)      { W = tw; bias = tb; out = g_th16; }
    else if (proj == 1) { W = pw; bias = pb; out = g_ph16; }
    else                { W = gw; bias = gb; out = g_gm16; }
    out += b * 131072;
    const float* xb = x + b * 262144;

    const int tid = threadIdx.x, lane = tid & 31, warp = tid >> 5;
    const int grp = lane >> 2, qid = lane & 3;
    const int m0w = (warp >> 1) * 64, n0w = (warp & 1) * 32;

    float acc[16][4];
    #pragma unroll
    for (int i = 0; i < 16; ++i) { acc[i][0]=0.f; acc[i][1]=0.f; acc[i][2]=0.f; acc[i][3]=0.f; }

    for (int k0 = 0; k0 < 256; k0 += 32) {
        #pragma unroll
        for (int idx = tid; idx < 128 * 8; idx += 128) {
            int m = idx >> 3, k4 = (idx & 7) << 2;
            *(float4*)&Wt[m * 36 + k4] = *(const float4*)&W[m * 256 + k0 + k4];
        }
        #pragma unroll
        for (int idx = tid; idx < 32 * 16; idx += 128) {
            int k = idx >> 4, n4 = (idx & 15) << 2;
            *(float4*)&Xt[k * 72 + n4] = *(const float4*)&xb[(k0 + k) * 1024 + n0 + n4];
        }
        __syncthreads();
        #pragma unroll
        for (int ks = 0; ks < 4; ++ks) {
            const int k = ks * 8;
            unsigned ah[4][4], al[4][4];
            #pragma unroll
            for (int mi = 0; mi < 4; ++mi) {
                int r = m0w + mi * 16 + grp;
                float f0 = Wt[r * 36 + k + qid];
                float f1 = Wt[(r + 8) * 36 + k + qid];
                float f2 = Wt[r * 36 + k + qid + 4];
                float f3 = Wt[(r + 8) * 36 + k + qid + 4];
                ah[mi][0] = tf32_rna(f0); al[mi][0] = tf32_rna(f0 - __uint_as_float(ah[mi][0]));
                ah[mi][1] = tf32_rna(f1); al[mi][1] = tf32_rna(f1 - __uint_as_float(ah[mi][1]));
                ah[mi][2] = tf32_rna(f2); al[mi][2] = tf32_rna(f2 - __uint_as_float(ah[mi][2]));
                ah[mi][3] = tf32_rna(f3); al[mi][3] = tf32_rna(f3 - __uint_as_float(ah[mi][3]));
            }
            #pragma unroll
            for (int ni = 0; ni < 4; ++ni) {
                int c = n0w + ni * 8 + grp;
                unsigned b0 = tf32_rna(Xt[(k + qid) * 72 + c]);
                unsigned b1 = tf32_rna(Xt[(k + qid + 4) * 72 + c]);
                #pragma unroll
                for (int mi = 0; mi < 4; ++mi) {
                    mma_tf32(acc[mi*4+ni], ah[mi][0], ah[mi][1], ah[mi][2], ah[mi][3], b0, b1);
                    mma_tf32(acc[mi*4+ni], al[mi][0], al[mi][1], al[mi][2], al[mi][3], b0, b1);
                }
            }
        }
        __syncthreads();
    }
    #pragma unroll
    for (int mi = 0; mi < 4; ++mi) {
        int m = m0w + mi * 16 + grp;
        float bv0 = bias[m], bv1 = bias[m + 8];
        #pragma unroll
        for (int ni = 0; ni < 4; ++ni) {
            int n = n0 + n0w + ni * 8 + 2 * qid;
            float* a = acc[mi*4+ni];
            *(__half2*)&out[m * 1024 + n]       = __floats2half2_rn(a[0] + bv0, a[1] + bv0);
            *(__half2*)&out[(m + 8) * 1024 + n] = __floats2half2_rn(a[2] + bv1, a[3] + bv1);
        }
    }
}

// ---------------------------------------------------------------------------
// Flash attention, fp16 mma.sync m16n8k16, ldmatrix fragments, cp.async
// pipelined, P kept in registers (FA2 repack), per-warp-col softmax state.
// 128 CTAs x 256 thr; 64 Q rows/CTA; KV tiles of 128.
// ---------------------------------------------------------------------------
#define KS_ST 136    // halves; 272B row stride -> conflict-free ldmatrix
#define GS_ST 136
#define OS_ST 132    // epilogue float staging stride
#define ATTN_SMEM (128*KS_ST*2 + 128*GS_ST*2 + 512)

__global__ void __launch_bounds__(256, 1) attn_mma_kernel()
{
    extern __shared__ char smc[];
    __half* Ks = (__half*)smc;                     // [128][136] halves: phi tile [k][n]
    __half* Gs = Ks + 128 * KS_ST;                 // [128][136] halves: g tile [kv][d]
    float*  red_m = (float*)(smc + 128*KS_ST*2 + 128*GS_ST*2);   // [64]
    float*  red_l = red_m + 64;                    // [64]
    float*  Os = (float*)smc;                      // epilogue staging [64][132] f32

    const int tid  = threadIdx.x;
    const int lane = tid & 31, warp = tid >> 5;
    const int wr = warp >> 1, wc = warp & 1;
    const int grp = lane >> 2, qid = lane & 3;
    const int r_lo = wr * 16 + grp, r_hi = r_lo + 8;
    const int cw0 = wc * 64;
    const int row0 = blockIdx.x * 64;

    const unsigned ks_u = (unsigned)__cvta_generic_to_shared(Ks);
    const unsigned gs_u = (unsigned)__cvta_generic_to_shared(Gs);

    // ---- stage Q through Ks, pick up A-fragments via ldmatrix.x4 ----
    #pragma unroll
    for (int idx = tid; idx < 64 * 16; idx += 256) {
        int r = idx >> 4, c8 = (idx & 15) << 3;
        *(uint4*)&Ks[r * KS_ST + c8] = *(const uint4*)&g_th16[(row0 + r) * 128 + c8];
    }
    __syncthreads();
    unsigned qa[8][4];
    {
        const int arow = wr * 16 + (lane & 7) + 8 * ((lane >> 3) & 1);
        const int ac8  = 8 * (lane >> 4);
        #pragma unroll
        for (int ksi = 0; ksi < 8; ++ksi)
            ldsm_x4(qa[ksi][0], qa[ksi][1], qa[ksi][2], qa[ksi][3],
                    ks_u + (arow * KS_ST + ksi * 16 + ac8) * 2);
    }
    __syncthreads();

    // ---- prologue: start K(0), G(0) streams ----
    #pragma unroll
    for (int idx = tid; idx < 128 * 16; idx += 256) {
        int k = idx >> 4, c8 = (idx & 15) << 3;
        cp16(ks_u + (k * KS_ST + c8) * 2, &g_ph16[k * N_TOT + c8]);
    }
    CP_COMMIT();
    #pragma unroll
    for (int idx = tid; idx < 128 * 16; idx += 256) {
        int kv = idx >> 4, c8 = (idx & 15) << 3;
        cp16(gs_u + (kv * GS_ST + c8) * 2, &g_gm16[kv * 128 + c8]);
    }
    CP_COMMIT();

    const int brow = (lane & 7) + 8 * ((lane >> 3) & 1);   // B-frag k-row (x2.trans)

    float m0 = NEG_INF, m1 = NEG_INF, l0 = 0.f, l1 = 0.f;
    float o[16][4];
    #pragma unroll
    for (int t = 0; t < 16; ++t) { o[t][0]=0.f; o[t][1]=0.f; o[t][2]=0.f; o[t][3]=0.f; }

    for (int it = 0; it < 64; ++it) {
        const int c0 = it * 128;
        CP_WAIT(1);             // K(it) ready (G(it) may still stream)
        __syncthreads();

        // ---- S = Q @ K (fp16 m16n8k16) ----
        float s[8][4];
        #pragma unroll
        for (int t = 0; t < 8; ++t) { s[t][0]=0.f; s[t][1]=0.f; s[t][2]=0.f; s[t][3]=0.f; }

        #pragma unroll
        for (int ksi = 0; ksi < 8; ++ksi) {
            const unsigned kaddr = ks_u + ((ksi * 16 + brow) * KS_ST + cw0) * 2;
            #pragma unroll
            for (int t = 0; t < 8; ++t) {
                unsigned b0, b1;
                ldsm_x2_t(b0, b1, kaddr + t * 16);
                mma_f16(s[t], qa[ksi][0], qa[ksi][1], qa[ksi][2], qa[ksi][3], b0, b1);
            }
        }
        __syncthreads();        // everyone done reading Ks

        if (it < 63) {          // stream K(it+1) during softmax + PV
            #pragma unroll
            for (int idx = tid; idx < 128 * 16; idx += 256) {
                int k = idx >> 4, c8 = (idx & 15) << 3;
                cp16(ks_u + (k * KS_ST + c8) * 2, &g_ph16[k * N_TOT + c0 + 128 + c8]);
            }
            CP_COMMIT();
        }

        // ---- online softmax (per warp-column state), P -> registers ----
        float mx0 = NEG_INF, mx1 = NEG_INF;
        #pragma unroll
        for (int t = 0; t < 8; ++t) {
            mx0 = fmaxf(mx0, fmaxf(s[t][0], s[t][1]));
            mx1 = fmaxf(mx1, fmaxf(s[t][2], s[t][3]));
        }
        mx0 = fmaxf(mx0, __shfl_xor_sync(0xffffffffu, mx0, 1));
        mx0 = fmaxf(mx0, __shfl_xor_sync(0xffffffffu, mx0, 2));
        mx1 = fmaxf(mx1, __shfl_xor_sync(0xffffffffu, mx1, 1));
        mx1 = fmaxf(mx1, __shfl_xor_sync(0xffffffffu, mx1, 2));
        float mn0 = fmaxf(m0, mx0), mn1 = fmaxf(m1, mx1);
        float corr0 = ex2((m0 - mn0) * L2E);
        float corr1 = ex2((m1 - mn1) * L2E);
        m0 = mn0; m1 = mn1;

        unsigned pa[4][4];
        float sum0 = 0.f, sum1 = 0.f;
        #pragma unroll
        for (int t = 0; t < 8; ++t) {
            __half2 hlo = __floats2half2_rn(ex2((s[t][0] - mn0) * L2E),
                                            ex2((s[t][1] - mn0) * L2E));
            __half2 hhi = __floats2half2_rn(ex2((s[t][2] - mn1) * L2E),
                                            ex2((s[t][3] - mn1) * L2E));
            float2 flo = __half22float2(hlo);
            float2 fhi = __half22float2(hhi);
            sum0 += flo.x + flo.y;
            sum1 += fhi.x + fhi.y;
            const int ksi = t >> 1, hi = (t & 1) << 1;
            pa[ksi][hi]     = h2u(hlo);
            pa[ksi][hi + 1] = h2u(hhi);
        }
        sum0 += __shfl_xor_sync(0xffffffffu, sum0, 1);
        sum0 += __shfl_xor_sync(0xffffffffu, sum0, 2);
        sum1 += __shfl_xor_sync(0xffffffffu, sum1, 1);
        sum1 += __shfl_xor_sync(0xffffffffu, sum1, 2);
        l0 = l0 * corr0 + sum0;
        l1 = l1 * corr1 + sum1;
        #pragma unroll
        for (int t = 0; t < 16; ++t) {
            o[t][0] *= corr0; o[t][1] *= corr0;
            o[t][2] *= corr1; o[t][3] *= corr1;
        }
        // fix fragment order: pa[ksi] = {row-lo k-lo, row-hi k-lo, row-lo k-hi, row-hi k-hi}
        // currently stored {lo0,hi0,lo1,hi1} per t-pair = {a0,a1,a2,a3} — correct as built.

        if (it < 63) CP_WAIT(1); else CP_WAIT(0);   // G(it) ready
        __syncthreads();

        // ---- O += P @ G (fp16), this warp-col's 64 KV rows ----
        #pragma unroll
        for (int ksi = 0; ksi < 4; ++ksi) {
            const unsigned gaddr = gs_u + ((cw0 + ksi * 16 + brow) * GS_ST) * 2;
            #pragma unroll
            for (int t = 0; t < 16; ++t) {
                unsigned b0, b1;
                ldsm_x2_t(b0, b1, gaddr + t * 16);
                mma_f16(o[t], pa[ksi][0], pa[ksi][1], pa[ksi][2], pa[ksi][3], b0, b1);
            }
        }
        __syncthreads();        // Gs reads done

        if (it < 63) {          // stream G(it+1) during next S
            #pragma unroll
            for (int idx = tid; idx < 128 * 16; idx += 256) {
                int kv = idx >> 4, c8 = (idx & 15) << 3;
                cp16(gs_u + (kv * GS_ST + c8) * 2, &g_gm16[(c0 + 128 + kv) * 128 + c8]);
            }
            CP_COMMIT();
        }
    }

    // ---- epilogue: merge the two warp-column partials (smem reused) ----
    if (wc == 1) {
        if (qid == 0) {
            red_m[r_lo] = m0; red_l[r_lo] = l0;
            red_m[r_hi] = m1; red_l[r_hi] = l1;
        }
        #pragma unroll
        for (int t = 0; t < 16; ++t) {
            int col = t * 8 + 2 * qid;
            *(float2*)&Os[r_lo * OS_ST + col] = make_float2(o[t][0], o[t][1]);
            *(float2*)&Os[r_hi * OS_ST + col] = make_float2(o[t][2], o[t][3]);
        }
    }
    __syncthreads();
    if (wc == 0) {
        float mo0 = red_m[r_lo], lo0 = red_l[r_lo];
        float mo1 = red_m[r_hi], lo1 = red_l[r_hi];
        float mf0 = fmaxf(m0, mo0), mf1 = fmaxf(m1, mo1);
        float ca0 = ex2((m0 - mf0) * L2E), cb0 = ex2((mo0 - mf0) * L2E);
        float ca1 = ex2((m1 - mf1) * L2E), cb1 = ex2((mo1 - mf1) * L2E);
        float inv0 = 1.f / (l0 * ca0 + lo0 * cb0);
        float inv1 = 1.f / (l1 * ca1 + lo1 * cb1);
        float sa0 = ca0 * inv0, sb0 = cb0 * inv0;
        float sa1 = ca1 * inv1, sb1 = cb1 * inv1;
        #pragma unroll
        for (int t = 0; t < 16; ++t) {
            int col = t * 8 + 2 * qid;
            float2 q0 = *(float2*)&Os[r_lo * OS_ST + col];
            float2 q1 = *(float2*)&Os[r_hi * OS_ST + col];
            *(float2*)&g_o[(row0 + r_lo) * 128 + col] =
                make_float2(o[t][0] * sa0 + q0.x * sb0, o[t][1] * sa0 + q0.y * sb0);
            *(float2*)&g_o[(row0 + r_hi) * 128 + col] =
                make_float2(o[t][2] * sa1 + q1.x * sb1, o[t][3] * sa1 + q1.y * sb1);
        }
    }
}

// ---------------------------------------------------------------------------
// Output projection + residual, tf32 MMA 2x-split (unchanged).
// ---------------------------------------------------------------------------
__global__ void __launch_bounds__(128) outproj_mma_kernel(
    const float* __restrict__ x,
    const float* __restrict__ Ww, const float* __restrict__ Wb,
    float* __restrict__ y)
{
    __shared__ float Wt[128 * 36];
    __shared__ float Ot[32 * 72];

    const int n0 = blockIdx.x * 64;
    const int m0 = blockIdx.y * 128;
    const int b  = blockIdx.z;
    const float* Ob = g_o + b * 131072;
    const float* xb = x + b * 262144;
    float* yb = y + b * 262144;

    const int tid = threadIdx.x, lane = tid & 31, warp = tid >> 5;
    const int grp = lane >> 2, qid = lane & 3;
    const int m0w = (warp >> 1) * 64, n0w = (warp & 1) * 32;

    float acc[16][4];
    #pragma unroll
    for (int i = 0; i < 16; ++i) { acc[i][0]=0.f; acc[i][1]=0.f; acc[i][2]=0.f; acc[i][3]=0.f; }

    for (int k0 = 0; k0 < 128; k0 += 32) {
        #pragma unroll
        for (int idx = tid; idx < 128 * 8; idx += 128) {
            int m = idx >> 3, k4 = (idx & 7) << 2;
            *(float4*)&Wt[m * 36 + k4] = *(const float4*)&Ww[(m0 + m) * 128 + k0 + k4];
        }
        #pragma unroll
        for (int idx = tid; idx < 32 * 16; idx += 128) {
            int k = idx >> 4, n4 = (idx & 15) << 2;
            *(float4*)&Ot[k * 72 + n4] = *(const float4*)&Ob[(k0 + k) * 1024 + n0 + n4];
        }
        __syncthreads();
        #pragma unroll
        for (int ks = 0; ks < 4; ++ks) {
            const int k = ks * 8;
            unsigned ah[4][4], al[4][4];
            #pragma unroll
            for (int mi = 0; mi < 4; ++mi) {
                int r = m0w + mi * 16 + grp;
                float f0 = Wt[r * 36 + k + qid];
                float f1 = Wt[(r + 8) * 36 + k + qid];
                float f2 = Wt[r * 36 + k + qid + 4];
                float f3 = Wt[(r + 8) * 36 + k + qid + 4];
                ah[mi][0] = tf32_rna(f0); al[mi][0] = tf32_rna(f0 - __uint_as_float(ah[mi][0]));
                ah[mi][1] = tf32_rna(f1); al[mi][1] = tf32_rna(f1 - __uint_as_float(ah[mi][1]));
                ah[mi][2] = tf32_rna(f2); al[mi][2] = tf32_rna(f2 - __uint_as_float(ah[mi][2]));
                ah[mi][3] = tf32_rna(f3); al[mi][3] = tf32_rna(f3 - __uint_as_float(ah[mi][3]));
            }
            #pragma unroll
            for (int ni = 0; ni < 4; ++ni) {
                int c = n0w + ni * 8 + grp;
                unsigned b0 = tf32_rna(Ot[(k + qid) * 72 + c]);
                unsigned b1 = tf32_rna(Ot[(k + qid + 4) * 72 + c]);
                #pragma unroll
                for (int mi = 0; mi < 4; ++mi) {
                    mma_tf32(acc[mi*4+ni], ah[mi][0], ah[mi][1], ah[mi][2], ah[mi][3], b0, b1);
                    mma_tf32(acc[mi*4+ni], al[mi][0], al[mi][1], al[mi][2], al[mi][3], b0, b1);
                }
            }
        }
        __syncthreads();
    }
    #pragma unroll
    for (int mi = 0; mi < 4; ++mi) {
        int m = m0 + m0w + mi * 16 + grp;
        float bv0 = Wb[m], bv1 = Wb[m + 8];
        #pragma unroll
        for (int ni = 0; ni < 4; ++ni) {
            int n = n0 + n0w + ni * 8 + 2 * qid;
            float* a = acc[mi*4+ni];
            float2 x0 = *(const float2*)&xb[m * 1024 + n];
            float2 x1 = *(const float2*)&xb[(m + 8) * 1024 + n];
            *(float2*)&yb[m * 1024 + n] =
                make_float2(a[0] + bv0 + x0.x, a[1] + bv0 + x0.y);
            *(float2*)&yb[(m + 8) * 1024 + n] =
                make_float2(a[2] + bv1 + x1.x, a[3] + bv1 + x1.y);
        }
    }
}

// ---------------------------------------------------------------------------
extern "C" void kernel_launch(void* const* d_in, const int* in_sizes, int n_in,
                              void* d_out, int out_size)
{
    const float* x  = (const float*)d_in[0];
    const float* tw = (const float*)d_in[1];
    const float* tb = (const float*)d_in[2];
    const float* pw = (const float*)d_in[3];
    const float* pb = (const float*)d_in[4];
    const float* gw = (const float*)d_in[5];
    const float* gb = (const float*)d_in[6];
    const float* Ww = (const float*)d_in[7];
    const float* Wb = (const float*)d_in[8];
    float* y = (float*)d_out;

    cudaFuncSetAttribute(attn_mma_kernel,
                         cudaFuncAttributeMaxDynamicSharedMemorySize, ATTN_SMEM);

    proj_mma_kernel<<<dim3(16, 3, 8), 128>>>(x, tw, tb, pw, pb, gw, gb);
    attn_mma_kernel<<<dim3(128), 256, ATTN_SMEM>>>();
    outproj_mma_kernel<<<dim3(16, 2, 8), 128>>>(x, Ww, Wb, y);
}

// round 7
// speedup vs baseline: 9.8767x; 1.0495x over previous
#include <cuda_runtime.h>
#include <cuda_fp16.h>

#define N_TOT 8192
#define L2E 1.4426950408889634f
#define NEG_INF (-1.0f/0.0f)

// scratch (allocation-free rule: device globals)
__device__ __half g_x16 [8 * 256 * 1024];   // x fp16, [B][C][HW]
__device__ __half g_tw16[128 * 256];
__device__ __half g_pw16[128 * 256];
__device__ __half g_gw16[128 * 256];
__device__ __half g_Ww16[256 * 128];
__device__ __half g_th16[N_TOT * 128];      // theta fp16 [8192][128] flat view
__device__ __half g_ph16[N_TOT * 128];      // phi   fp16, viewed [128][8192]
__device__ __half g_gm16[N_TOT * 128];      // g     fp16 [8192][128]
__device__ __half g_o16 [N_TOT * 128];      // attn out fp16 [8192][128]

// ---------------------------------------------------------------------------
// helpers
// ---------------------------------------------------------------------------
__device__ __forceinline__ float ex2(float x) {
    float y; asm("ex2.approx.f32 %0, %1;" : "=f"(y) : "f"(x)); return y;
}
__device__ __forceinline__ void mma_f16(float c[4],
    unsigned a0, unsigned a1, unsigned a2, unsigned a3, unsigned b0, unsigned b1)
{
    asm volatile(
        "mma.sync.aligned.m16n8k16.row.col.f32.f16.f16.f32 "
        "{%0,%1,%2,%3}, {%4,%5,%6,%7}, {%8,%9}, {%0,%1,%2,%3};\n"
        : "+f"(c[0]), "+f"(c[1]), "+f"(c[2]), "+f"(c[3])
        : "r"(a0), "r"(a1), "r"(a2), "r"(a3), "r"(b0), "r"(b1));
}
__device__ __forceinline__ void ldsm_x4(unsigned& r0, unsigned& r1,
                                        unsigned& r2, unsigned& r3, unsigned addr)
{
    asm volatile("ldmatrix.sync.aligned.m8n8.x4.shared.b16 {%0,%1,%2,%3}, [%4];"
                 : "=r"(r0), "=r"(r1), "=r"(r2), "=r"(r3) : "r"(addr));
}
__device__ __forceinline__ void ldsm_x4_t(unsigned& r0, unsigned& r1,
                                          unsigned& r2, unsigned& r3, unsigned addr)
{
    asm volatile("ldmatrix.sync.aligned.m8n8.x4.trans.shared.b16 {%0,%1,%2,%3}, [%4];"
                 : "=r"(r0), "=r"(r1), "=r"(r2), "=r"(r3) : "r"(addr));
}
__device__ __forceinline__ unsigned h2u(__half2 h) {
    return *reinterpret_cast<unsigned*>(&h);
}
__device__ __forceinline__ void cp16(unsigned smem_addr, const void* gptr) {
    asm volatile("cp.async.cg.shared.global [%0], [%1], 16;\n"
                 :: "r"(smem_addr), "l"(gptr));
}
#define CP_COMMIT() asm volatile("cp.async.commit_group;\n" ::: "memory")
#define CP_WAIT(n)  asm volatile("cp.async.wait_group %0;\n" :: "n"(n) : "memory")

// ---------------------------------------------------------------------------
// prep: fp32 -> fp16 conversions (x + all weights), once.
// ---------------------------------------------------------------------------
__global__ void __launch_bounds__(256) prep_kernel(
    const float* __restrict__ x,  const float* __restrict__ tw,
    const float* __restrict__ pw, const float* __restrict__ gw,
    const float* __restrict__ Ww)
{
    int i = blockIdx.x * 256 + threadIdx.x;      // pair index
    if (i < 1048576) {
        float2 v = ((const float2*)x)[i];
        *(__half2*)&g_x16[2*i] = __floats2half2_rn(v.x, v.y);
    }
    if (i < 16384) {
        float2 a = ((const float2*)tw)[i];
        *(__half2*)&g_tw16[2*i] = __floats2half2_rn(a.x, a.y);
        float2 b = ((const float2*)pw)[i];
        *(__half2*)&g_pw16[2*i] = __floats2half2_rn(b.x, b.y);
        float2 c = ((const float2*)gw)[i];
        *(__half2*)&g_gw16[2*i] = __floats2half2_rn(c.x, c.y);
        float2 d = ((const float2*)Ww)[i];
        *(__half2*)&g_Ww16[2*i] = __floats2half2_rn(d.x, d.y);
    }
}

// ---------------------------------------------------------------------------
// Projections, pure fp16 MMA. grid (16 n-tiles, 3 projs, 8 b), 256 threads.
// out[m][n] = sum_c W[m][c] x[c][n] + bias[m];  warp grid 4m(32) x 2n(32).
// ---------------------------------------------------------------------------
__global__ void __launch_bounds__(256) proj16_kernel(
    const float* __restrict__ tb, const float* __restrict__ pb,
    const float* __restrict__ gb)
{
    __shared__ __half Wt[128 * 72];   // [m 128][k 64]
    __shared__ __half Xt[64 * 72];    // [k 64][n 64]

    const int n0 = blockIdx.x * 64;
    const int proj = blockIdx.y;
    const int b = blockIdx.z;

    const __half* W16; const float* bias; __half* out;
    if (proj == 0)      { W16 = g_tw16; bias = tb; out = g_th16; }
    else if (proj == 1) { W16 = g_pw16; bias = pb; out = g_ph16; }
    else                { W16 = g_gw16; bias = gb; out = g_gm16; }
    out += b * 131072;
    const __half* xb = g_x16 + b * 262144;

    const int tid = threadIdx.x, lane = tid & 31, warp = tid >> 5;
    const int grp = lane >> 2, qid = lane & 3;
    const int m0w = (warp >> 1) * 32, n0w = (warp & 1) * 32;
    const int brow = (lane & 7) + 8 * ((lane >> 3) & 1);
    const int c8b = 8 * (lane >> 4);
    const unsigned wt_u = (unsigned)__cvta_generic_to_shared(Wt);
    const unsigned xt_u = (unsigned)__cvta_generic_to_shared(Xt);

    float acc[8][4];
    #pragma unroll
    for (int i = 0; i < 8; ++i) { acc[i][0]=0.f; acc[i][1]=0.f; acc[i][2]=0.f; acc[i][3]=0.f; }

    for (int k0 = 0; k0 < 256; k0 += 64) {
        #pragma unroll
        for (int idx = tid; idx < 128 * 8; idx += 256) {
            int m = idx >> 3, c8 = (idx & 7) << 3;
            *(uint4*)&Wt[m * 72 + c8] = *(const uint4*)&W16[m * 256 + k0 + c8];
        }
        #pragma unroll
        for (int idx = tid; idx < 64 * 8; idx += 256) {
            int k = idx >> 3, c8 = (idx & 7) << 3;
            *(uint4*)&Xt[k * 72 + c8] = *(const uint4*)&xb[(k0 + k) * 1024 + n0 + c8];
        }
        __syncthreads();
        #pragma unroll
        for (int ksi = 0; ksi < 4; ++ksi) {
            unsigned a[2][4];
            #pragma unroll
            for (int mi = 0; mi < 2; ++mi)
                ldsm_x4(a[mi][0], a[mi][1], a[mi][2], a[mi][3],
                        wt_u + ((m0w + mi * 16 + brow) * 72 + ksi * 16 + c8b) * 2);
            #pragma unroll
            for (int t2 = 0; t2 < 2; ++t2) {
                unsigned b0, b1, b2, b3;
                ldsm_x4_t(b0, b1, b2, b3,
                          xt_u + ((ksi * 16 + brow) * 72 + n0w + t2 * 16 + c8b) * 2);
                #pragma unroll
                for (int mi = 0; mi < 2; ++mi) {
                    mma_f16(acc[mi*4 + t2*2],     a[mi][0], a[mi][1], a[mi][2], a[mi][3], b0, b1);
                    mma_f16(acc[mi*4 + t2*2 + 1], a[mi][0], a[mi][1], a[mi][2], a[mi][3], b2, b3);
                }
            }
        }
        __syncthreads();
    }
    #pragma unroll
    for (int mi = 0; mi < 2; ++mi) {
        int m = m0w + mi * 16 + grp;
        float bv0 = bias[m], bv1 = bias[m + 8];
        #pragma unroll
        for (int t = 0; t < 4; ++t) {
            int col = n0 + n0w + t * 8 + 2 * qid;
            float* a = acc[mi*4 + t];
            *(__half2*)&out[m * 1024 + col]       = __floats2half2_rn(a[0] + bv0, a[1] + bv0);
            *(__half2*)&out[(m + 8) * 1024 + col] = __floats2half2_rn(a[2] + bv1, a[3] + bv1);
        }
    }
}

// ---------------------------------------------------------------------------
// Flash attention, fp16 mma, 512 threads (4 row-groups x 4 kv-col-groups),
// cp.async pipelined, P in registers, 4-way split-KV merged in epilogue.
// 128 CTAs; 64 Q rows/CTA; KV tiles of 128.
// ---------------------------------------------------------------------------
#define QS_ST 136
#define KS_ST 136
#define GS_ST 136
#define ATTN_SMEM ((64*QS_ST + 128*KS_ST + 128*GS_ST) * 2 + 2048)

__global__ void __launch_bounds__(512, 1) attn_mma_kernel()
{
    extern __shared__ char smc[];
    __half* Qs = (__half*)smc;                   // [64][136] resident
    __half* Ks = Qs + 64 * QS_ST;                // [128][136] phi tile [k][n]
    __half* Gs = Ks + 128 * KS_ST;               // [128][136] g tile [kv][d]
    float* red_m = (float*)(smc + (64*QS_ST + 128*KS_ST + 128*GS_ST) * 2); // [4][64]
    float* red_l = red_m + 256;                  // [4][64]
    float* bufA = (float*)smc;                   // epilogue staging [64][132]
    float* bufB = bufA + 64 * 132;

    const int tid  = threadIdx.x;
    const int lane = tid & 31, warp = tid >> 5;
    const int wr = warp >> 2, wc = warp & 3;
    const int grp = lane >> 2, qid = lane & 3;
    const int r_lo = wr * 16 + grp, r_hi = r_lo + 8;
    const int cw0 = wc * 32;
    const int row0 = blockIdx.x * 64;
    const int brow = (lane & 7) + 8 * ((lane >> 3) & 1);
    const int c8b  = 8 * (lane >> 4);

    const unsigned qs_u = (unsigned)__cvta_generic_to_shared(Qs);
    const unsigned ks_u = (unsigned)__cvta_generic_to_shared(Ks);
    const unsigned gs_u = (unsigned)__cvta_generic_to_shared(Gs);
    const unsigned qfrag = qs_u + ((wr * 16 + brow) * QS_ST + c8b) * 2;

    // prologue: start K(0), G(0) streams
    #pragma unroll
    for (int idx = tid; idx < 128 * 16; idx += 512) {
        int k = idx >> 4, c8 = (idx & 15) << 3;
        cp16(ks_u + (k * KS_ST + c8) * 2, &g_ph16[k * N_TOT + c8]);
    }
    CP_COMMIT();
    #pragma unroll
    for (int idx = tid; idx < 128 * 16; idx += 512) {
        int kv = idx >> 4, c8 = (idx & 15) << 3;
        cp16(gs_u + (kv * GS_ST + c8) * 2, &g_gm16[kv * 128 + c8]);
    }
    CP_COMMIT();

    // stage Q (resident all iterations)
    #pragma unroll
    for (int idx = tid; idx < 64 * 16; idx += 512) {
        int r = idx >> 4, c8 = (idx & 15) << 3;
        *(uint4*)&Qs[r * QS_ST + c8] = *(const uint4*)&g_th16[(row0 + r) * 128 + c8];
    }

    float m0 = NEG_INF, m1 = NEG_INF, l0 = 0.f, l1 = 0.f;
    float o[16][4];
    #pragma unroll
    for (int t = 0; t < 16; ++t) { o[t][0]=0.f; o[t][1]=0.f; o[t][2]=0.f; o[t][3]=0.f; }

    for (int it = 0; it < 64; ++it) {
        const int c0 = it * 128;
        CP_WAIT(1);             // K(it) ready (G(it) may still stream)
        __syncthreads();

        // ---- S = Q @ K ----
        float s[4][4];
        #pragma unroll
        for (int t = 0; t < 4; ++t) { s[t][0]=0.f; s[t][1]=0.f; s[t][2]=0.f; s[t][3]=0.f; }

        #pragma unroll
        for (int ksi = 0; ksi < 8; ++ksi) {
            unsigned a0, a1, a2, a3;
            ldsm_x4(a0, a1, a2, a3, qfrag + (ksi * 16) * 2);
            #pragma unroll
            for (int t2 = 0; t2 < 2; ++t2) {
                unsigned b0, b1, b2, b3;
                ldsm_x4_t(b0, b1, b2, b3,
                          ks_u + ((ksi * 16 + brow) * KS_ST + cw0 + t2 * 16 + c8b) * 2);
                mma_f16(s[t2*2],     a0, a1, a2, a3, b0, b1);
                mma_f16(s[t2*2 + 1], a0, a1, a2, a3, b2, b3);
            }
        }
        __syncthreads();        // done reading Ks

        if (it < 63) {          // stream K(it+1) during softmax + PV
            #pragma unroll
            for (int idx = tid; idx < 128 * 16; idx += 512) {
                int k = idx >> 4, c8 = (idx & 15) << 3;
                cp16(ks_u + (k * KS_ST + c8) * 2, &g_ph16[k * N_TOT + c0 + 128 + c8]);
            }
            CP_COMMIT();
        }

        // ---- online softmax (per kv-col-group state) ----
        float mx0 = fmaxf(fmaxf(s[0][0], s[0][1]), fmaxf(s[1][0], s[1][1]));
        mx0 = fmaxf(mx0, fmaxf(fmaxf(s[2][0], s[2][1]), fmaxf(s[3][0], s[3][1])));
        float mx1 = fmaxf(fmaxf(s[0][2], s[0][3]), fmaxf(s[1][2], s[1][3]));
        mx1 = fmaxf(mx1, fmaxf(fmaxf(s[2][2], s[2][3]), fmaxf(s[3][2], s[3][3])));
        mx0 = fmaxf(mx0, __shfl_xor_sync(0xffffffffu, mx0, 1));
        mx0 = fmaxf(mx0, __shfl_xor_sync(0xffffffffu, mx0, 2));
        mx1 = fmaxf(mx1, __shfl_xor_sync(0xffffffffu, mx1, 1));
        mx1 = fmaxf(mx1, __shfl_xor_sync(0xffffffffu, mx1, 2));
        float mn0 = fmaxf(m0, mx0), mn1 = fmaxf(m1, mx1);
        float corr0 = ex2((m0 - mn0) * L2E);
        float corr1 = ex2((m1 - mn1) * L2E);
        m0 = mn0; m1 = mn1;

        unsigned pa[2][4];
        float sum0 = 0.f, sum1 = 0.f;
        #pragma unroll
        for (int t = 0; t < 4; ++t) {
            __half2 hlo = __floats2half2_rn(ex2((s[t][0] - mn0) * L2E),
                                            ex2((s[t][1] - mn0) * L2E));
            __half2 hhi = __floats2half2_rn(ex2((s[t][2] - mn1) * L2E),
                                            ex2((s[t][3] - mn1) * L2E));
            float2 flo = __half22float2(hlo);
            float2 fhi = __half22float2(hhi);
            sum0 += flo.x + flo.y;
            sum1 += fhi.x + fhi.y;
            const int k2 = t >> 1, hi = (t & 1) << 1;
            pa[k2][hi]     = h2u(hlo);
            pa[k2][hi + 1] = h2u(hhi);
        }
        sum0 += __shfl_xor_sync(0xffffffffu, sum0, 1);
        sum0 += __shfl_xor_sync(0xffffffffu, sum0, 2);
        sum1 += __shfl_xor_sync(0xffffffffu, sum1, 1);
        sum1 += __shfl_xor_sync(0xffffffffu, sum1, 2);
        l0 = l0 * corr0 + sum0;
        l1 = l1 * corr1 + sum1;
        #pragma unroll
        for (int t = 0; t < 16; ++t) {
            o[t][0] *= corr0; o[t][1] *= corr0;
            o[t][2] *= corr1; o[t][3] *= corr1;
        }

        if (it < 63) CP_WAIT(1); else CP_WAIT(0);   // G(it) ready
        __syncthreads();

        // ---- O += P @ G, this warp's 32 KV rows ----
        #pragma unroll
        for (int k2 = 0; k2 < 2; ++k2) {
            #pragma unroll
            for (int t2 = 0; t2 < 8; ++t2) {
                unsigned b0, b1, b2, b3;
                ldsm_x4_t(b0, b1, b2, b3,
                          gs_u + ((cw0 + k2 * 16 + brow) * GS_ST + t2 * 16 + c8b) * 2);
                mma_f16(o[t2*2],     pa[k2][0], pa[k2][1], pa[k2][2], pa[k2][3], b0, b1);
                mma_f16(o[t2*2 + 1], pa[k2][0], pa[k2][1], pa[k2][2], pa[k2][3], b2, b3);
            }
        }
        __syncthreads();        // Gs reads done

        if (it < 63) {          // stream G(it+1) during next S
            #pragma unroll
            for (int idx = tid; idx < 128 * 16; idx += 512) {
                int kv = idx >> 4, c8 = (idx & 15) << 3;
                cp16(gs_u + (kv * GS_ST + c8) * 2, &g_gm16[(c0 + 128 + kv) * 128 + c8]);
            }
            CP_COMMIT();
        }
    }

    // ---- epilogue: merge 4 kv-col-group partials ----
    if (qid == 0) {
        red_m[wc * 64 + r_lo] = m0;
        red_m[wc * 64 + r_hi] = m1;
    }
    __syncthreads();
    float mf0 = fmaxf(fmaxf(red_m[r_lo], red_m[64 + r_lo]),
                      fmaxf(red_m[128 + r_lo], red_m[192 + r_lo]));
    float mf1 = fmaxf(fmaxf(red_m[r_hi], red_m[64 + r_hi]),
                      fmaxf(red_m[128 + r_hi], red_m[192 + r_hi]));
    float sc0 = ex2((m0 - mf0) * L2E), sc1 = ex2((m1 - mf1) * L2E);
    #pragma unroll
    for (int t = 0; t < 16; ++t) {
        o[t][0] *= sc0; o[t][1] *= sc0;
        o[t][2] *= sc1; o[t][3] *= sc1;
    }
    if (qid == 0) {
        red_l[wc * 64 + r_lo] = l0 * sc0;
        red_l[wc * 64 + r_hi] = l1 * sc1;
    }
    if (wc == 1 || wc == 3) {
        float* buf = (wc == 1) ? bufA : bufB;
        #pragma unroll
        for (int t = 0; t < 16; ++t) {
            int col = t * 8 + 2 * qid;
            *(float2*)&buf[r_lo * 132 + col] = make_float2(o[t][0], o[t][1]);
            *(float2*)&buf[r_hi * 132 + col] = make_float2(o[t][2], o[t][3]);
        }
    }
    __syncthreads();
    if (wc == 0 || wc == 2) {
        float* buf = (wc == 0) ? bufA : bufB;
        #pragma unroll
        for (int t = 0; t < 16; ++t) {
            int col = t * 8 + 2 * qid;
            float2 v0 = *(float2*)&buf[r_lo * 132 + col];
            float2 v1 = *(float2*)&buf[r_hi * 132 + col];
            o[t][0] += v0.x; o[t][1] += v0.y;
            o[t][2] += v1.x; o[t][3] += v1.y;
        }
    }
    __syncthreads();
    if (wc == 2) {
        #pragma unroll
        for (int t = 0; t < 16; ++t) {
            int col = t * 8 + 2 * qid;
            *(float2*)&bufA[r_lo * 132 + col] = make_float2(o[t][0], o[t][1]);
            *(float2*)&bufA[r_hi * 132 + col] = make_float2(o[t][2], o[t][3]);
        }
    }
    __syncthreads();
    if (wc == 0) {
        float ls0 = red_l[r_lo] + red_l[64 + r_lo] + red_l[128 + r_lo] + red_l[192 + r_lo];
        float ls1 = red_l[r_hi] + red_l[64 + r_hi] + red_l[128 + r_hi] + red_l[192 + r_hi];
        float inv0 = 1.f / ls0, inv1 = 1.f / ls1;
        #pragma unroll
        for (int t = 0; t < 16; ++t) {
            int col = t * 8 + 2 * qid;
            float2 v0 = *(float2*)&bufA[r_lo * 132 + col];
            float2 v1 = *(float2*)&bufA[r_hi * 132 + col];
            *(__half2*)&g_o16[(row0 + r_lo) * 128 + col] =
                __floats2half2_rn((o[t][0] + v0.x) * inv0, (o[t][1] + v0.y) * inv0);
            *(__half2*)&g_o16[(row0 + r_hi) * 128 + col] =
                __floats2half2_rn((o[t][2] + v1.x) * inv1, (o[t][3] + v1.y) * inv1);
        }
    }
}

// ---------------------------------------------------------------------------
// Output projection + residual, fp16 MMA. grid (16 n-tiles, 8 b), 256 thr.
// y[m][n] = sum_k Ww[m][k] O[k][n] + Wb[m] + x[m][n];  warps 4m(64) x 2n(32).
// ---------------------------------------------------------------------------
__global__ void __launch_bounds__(256) outproj16_kernel(
    const float* __restrict__ x, const float* __restrict__ Wb,
    float* __restrict__ y)
{
    __shared__ __half Wt[256 * 72];   // [m 256][k 64]
    __shared__ __half Ot[64 * 72];    // [k 64][n 64]

    const int n0 = blockIdx.x * 64;
    const int b  = blockIdx.y;
    const __half* Ob = g_o16 + b * 131072;
    const float* xb = x + b * 262144;
    float* yb = y + b * 262144;

    const int tid = threadIdx.x, lane = tid & 31, warp = tid >> 5;
    const int grp = lane >> 2, qid = lane & 3;
    const int m0w = (warp >> 1) * 64, n0w = (warp & 1) * 32;
    const int brow = (lane & 7) + 8 * ((lane >> 3) & 1);
    const int c8b = 8 * (lane >> 4);
    const unsigned wt_u = (unsigned)__cvta_generic_to_shared(Wt);
    const unsigned ot_u = (unsigned)__cvta_generic_to_shared(Ot);

    float acc[16][4];
    #pragma unroll
    for (int i = 0; i < 16; ++i) { acc[i][0]=0.f; acc[i][1]=0.f; acc[i][2]=0.f; acc[i][3]=0.f; }

    for (int k0 = 0; k0 < 128; k0 += 64) {
        #pragma unroll
        for (int idx = tid; idx < 256 * 8; idx += 256) {
            int m = idx >> 3, c8 = (idx & 7) << 3;
            *(uint4*)&Wt[m * 72 + c8] = *(const uint4*)&g_Ww16[m * 128 + k0 + c8];
        }
        #pragma unroll
        for (int idx = tid; idx < 64 * 8; idx += 256) {
            int k = idx >> 3, c8 = (idx & 7) << 3;
            *(uint4*)&Ot[k * 72 + c8] = *(const uint4*)&Ob[(k0 + k) * 1024 + n0 + c8];
        }
        __syncthreads();
        #pragma unroll
        for (int ksi = 0; ksi < 4; ++ksi) {
            unsigned a[4][4];
            #pragma unroll
            for (int mi = 0; mi < 4; ++mi)
                ldsm_x4(a[mi][0], a[mi][1], a[mi][2], a[mi][3],
                        wt_u + ((m0w + mi * 16 + brow) * 72 + ksi * 16 + c8b) * 2);
            #pragma unroll
            for (int t2 = 0; t2 < 2; ++t2) {
                unsigned b0, b1, b2, b3;
                ldsm_x4_t(b0, b1, b2, b3,
                          ot_u + ((ksi * 16 + brow) * 72 + n0w + t2 * 16 + c8b) * 2);
                #pragma unroll
                for (int mi = 0; mi < 4; ++mi) {
                    mma_f16(acc[mi*4 + t2*2],     a[mi][0], a[mi][1], a[mi][2], a[mi][3], b0, b1);
                    mma_f16(acc[mi*4 + t2*2 + 1], a[mi][0], a[mi][1], a[mi][2], a[mi][3], b2, b3);
                }
            }
        }
        __syncthreads();
    }
    #pragma unroll
    for (int mi = 0; mi < 4; ++mi) {
        int m = m0w + mi * 16 + grp;
        float bv0 = Wb[m], bv1 = Wb[m + 8];
        #pragma unroll
        for (int t = 0; t < 4; ++t) {
            int col = n0 + n0w + t * 8 + 2 * qid;
            float* a = acc[mi*4 + t];
            float2 x0 = *(const float2*)&xb[m * 1024 + col];
            float2 x1 = *(const float2*)&xb[(m + 8) * 1024 + col];
            *(float2*)&yb[m * 1024 + col] =
                make_float2(a[0] + bv0 + x0.x, a[1] + bv0 + x0.y);
            *(float2*)&yb[(m + 8) * 1024 + col] =
                make_float2(a[2] + bv1 + x1.x, a[3] + bv1 + x1.y);
        }
    }
}

// ---------------------------------------------------------------------------
extern "C" void kernel_launch(void* const* d_in, const int* in_sizes, int n_in,
                              void* d_out, int out_size)
{
    const float* x  = (const float*)d_in[0];
    const float* tw = (const float*)d_in[1];
    const float* tb = (const float*)d_in[2];
    const float* pw = (const float*)d_in[3];
    const float* pb = (const float*)d_in[4];
    const float* gw = (const float*)d_in[5];
    const float* gb = (const float*)d_in[6];
    const float* Ww = (const float*)d_in[7];
    const float* Wb = (const float*)d_in[8];
    float* y = (float*)d_out;

    cudaFuncSetAttribute(attn_mma_kernel,
                         cudaFuncAttributeMaxDynamicSharedMemorySize, ATTN_SMEM);

    prep_kernel<<<4096, 256>>>(x, tw, pw, gw, Ww);
    proj16_kernel<<<dim3(16, 3, 8), 256>>>(tb, pb, gb);
    attn_mma_kernel<<<dim3(128), 512, ATTN_SMEM>>>();
    outproj16_kernel<<<dim3(16, 8), 256>>>(x, Wb, y);
}